// round 14
// baseline (speedup 1.0000x reference)
#include <cuda_runtime.h>
#include <math.h>

// ---------- static scratch ----------
__device__ float g_h1[67108864];
__device__ float g_h2[33554432];
__device__ float g_h3[16777216];
__device__ float g_d1[67108864];
__device__ float g_d2[33554432];
__device__ float g_d3[16777216];
__device__ float g_fam[4194304];
__device__ float g_xm[4194304];
__device__ float g_att[524288];
__device__ float g_attp[4194304];
__device__ float g_alpha[4096];
__device__ float g_dsb[4096];
__device__ float g_dap[32768];
__device__ float g_mu[131072];
__device__ float g_m2[131072];
__device__ float g_dMu[131072];
__device__ float g_dE2[131072];
__device__ float g_gvec[8192];
__device__ float g_cat[262144];
__device__ float g_ep[1048576];
__device__ float g_cm[4096];
__device__ float g_tm[32768];
__device__ float g_meanT[4096];
__device__ float g_meanF[32768];
__device__ int   g_sc[4096];
__device__ int   g_st[4096];
__device__ int   g_rstep[4096];
__device__ int   g_cstep[32768];
__device__ int   g_rowp[4128];    // 32 * 129
__device__ int   g_colp[32800];   // 32 * 1025
__device__ float g_wtf2[73728];
__device__ float g_wtb2[73728];
__device__ float g_wtf3[294912];
__device__ float g_wtb3[294912];

// ---------- weight transposes ----------
__global__ void k_wt(const float* __restrict__ W, float* __restrict__ WTf,
                     float* __restrict__ WTb, int CIN, int COUT)
{
  int idx=blockIdx.x*256+threadIdx.x;
  int tot=CIN*COUT*9; if(idx>=tot) return;
  int k=idx%9, c=(idx/9)%CIN, o=idx/(9*CIN);
  float v=W[idx];
  int rf=(c>>3)*72 + k*8 + (c&7);
  WTf[(long)rf*COUT+o]=v;
  int rb=(o>>3)*72 + k*8 + (o&7);
  WTb[(long)rb*CIN+c]=v;
}

// ---------- conv1 fwd: 128-col tiles, 8 cols x 4 outs per thread ----------
// rowp/colp non-null => pass-2 mode: skip tiles whose receptive field is unmasked
__global__ void __launch_bounds__(256) k_conv1(
    const float* __restrict__ in, const float* __restrict__ W,
    const float* __restrict__ bias, float* __restrict__ out,
    const int* __restrict__ rowp, const int* __restrict__ colp)
{
  __shared__ __align__(16) float ins[3][264];
  __shared__ __align__(16) float ws[9][64];
  __shared__ float bs[64];
  const int n=blockIdx.z, i=blockIdx.y, j0=blockIdx.x*128;
  if(rowp){
    int r0=2*i, r1=2*i+3; if(r1>128) r1=128;
    int c0=2*j0, c1=2*j0+257; if(c1>1024) c1=1024;
    if(rowp[n*129+r1]==rowp[n*129+r0] && colp[n*1025+c1]==colp[n*1025+c0]) return;
  }
  const int tid=threadIdx.x, jt=tid&15, og=tid>>4;
  for(int idx=tid; idx<576; idx+=256){
    int o=idx/9, k=idx%9;
    ws[k][o]=W[idx];
  }
  if(tid<64) bs[tid]=bias[tid];
  for(int idx=tid; idx<3*258; idx+=256){
    int r=idx/258, col=idx%258;
    int gx=2*i+r, gy=2*j0+col;
    float v=0.f;
    if(gx<128 && gy<1024) v=in[((long)n*128+gx)*1024+gy];
    ins[r][col]=v;
  }
  __syncthreads();
  float acc[4][8];
#pragma unroll
  for(int o=0;o<4;o++)
#pragma unroll
  for(int e=0;e<8;e++) acc[o][e]=0.f;
#pragma unroll
  for(int r=0;r<3;r++){
    float v[17];
    *(float4*)v      = *(float4*)&ins[r][16*jt];
    *(float4*)(v+4)  = *(float4*)&ins[r][16*jt+4];
    *(float4*)(v+8)  = *(float4*)&ins[r][16*jt+8];
    *(float4*)(v+12) = *(float4*)&ins[r][16*jt+12];
    v[16]            = ins[r][16*jt+16];
#pragma unroll
    for(int kj=0;kj<3;kj++){
      float w[4];
      *(float4*)w = *(float4*)&ws[r*3+kj][og*4];
#pragma unroll
      for(int oo=0;oo<4;oo++)
#pragma unroll
      for(int e=0;e<8;e++)
        acc[oo][e]+=w[oo]*v[2*e+kj];
    }
  }
#pragma unroll
  for(int oo=0;oo<4;oo++){
    int o=og*4+oo;
    float bb=bs[o];
    float4 r0,r1;
    r0.x=fmaxf(acc[oo][0]+bb,0.f); r0.y=fmaxf(acc[oo][1]+bb,0.f);
    r0.z=fmaxf(acc[oo][2]+bb,0.f); r0.w=fmaxf(acc[oo][3]+bb,0.f);
    r1.x=fmaxf(acc[oo][4]+bb,0.f); r1.y=fmaxf(acc[oo][5]+bb,0.f);
    r1.z=fmaxf(acc[oo][6]+bb,0.f); r1.w=fmaxf(acc[oo][7]+bb,0.f);
    long base=(((long)n*64+o)*64+i)*512 + j0 + 8*jt;
    *(float4*)&out[base]=r0;
    *(float4*)&out[base+4]=r1;
  }
}

// ---------- tf32 helpers ----------
__device__ __forceinline__ float to_tf32(float v){
  unsigned r; asm("cvt.rna.tf32.f32 %0, %1;" : "=r"(r) : "f"(v));
  return __uint_as_float(r);
}
__device__ __forceinline__ void mma_tf32(float* c4,
    unsigned a0,unsigned a1,unsigned a2,unsigned a3,unsigned b0,unsigned b1){
  asm volatile(
    "mma.sync.aligned.m16n8k8.row.col.f32.tf32.tf32.f32 "
    "{%0,%1,%2,%3},{%4,%5,%6,%7},{%8,%9},{%0,%1,%2,%3};"
    : "+f"(c4[0]),"+f"(c4[1]),"+f"(c4[2]),"+f"(c4[3])
    : "r"(a0),"r"(a1),"r"(a2),"r"(a3),"r"(b0),"r"(b1));
}

// ---------- tf32 mma conv fwd; staging-side cvt ----------
template<int CIN,int COUT,int HIN,int WIN,int SPLIT>
__global__ void __launch_bounds__(256,2) k_cmma(
    const float* __restrict__ in, const float* __restrict__ WT,
    const float* __restrict__ bias, float* __restrict__ out)
{
  constexpr int HOUT=HIN/2, WOUT=WIN/2;
  constexpr int NJT=WOUT/128;
  constexpr int LD=136;
  constexpr int WOFF=(SPLIT==3)?96:48;
  extern __shared__ float sm[];
  float* evh = sm;
  float* odh = sm + 24*LD;
  float* evl = sm + 48*LD;
  float* odl = sm + 72*LD;
  float* ws  = sm + WOFF*LD;
  const int n=blockIdx.z, i=blockIdx.y;
  const int jt_=blockIdx.x%NJT, ot=blockIdx.x/NJT;
  const int j0=jt_*128, o0=ot*128;
  const int tid=threadIdx.x, wid=tid>>5, lane=tid&31;
  const int gid=lane>>2, tig=lane&3;
  const int m0=(wid&3)*32, n0w=(wid>>2)*64;
  float acc[2][8][4];
#pragma unroll
  for(int a=0;a<2;a++)
#pragma unroll
  for(int b=0;b<8;b++)
#pragma unroll
  for(int c=0;c<4;c++) acc[a][b][c]=0.f;

  for(int c0=0;c0<CIN;c0+=8){
    __syncthreads();
    for(int idx=tid; idx<8*3*129; idx+=256){
      int c=idx/387, rem=idx%387, r=rem/129, p=rem%129;
      int gx=2*i+r, gy=2*j0+2*p;
      float a=0.f,bv=0.f;
      if(gx<HIN && gy<WIN){
        const float2 s=*(const float2*)&in[(((long)n*CIN+c0+c)*HIN+gx)*WIN+gy];
        a=s.x; bv=s.y;
      }
      float ah=to_tf32(a), bh=to_tf32(bv);
      evh[(c*3+r)*LD+p]=ah;
      odh[(c*3+r)*LD+p]=bh;
      if(SPLIT==3){
        evl[(c*3+r)*LD+p]=to_tf32(a-ah);
        odl[(c*3+r)*LD+p]=to_tf32(bv-bh);
      }
    }
    {
      const float* wsrc = WT + (long)(c0>>3)*72*COUT + o0;
      for(int idx=tid; idx<72*32; idx+=256){
        int kk=idx>>5, o4=(idx&31)*4;
        float4 v=*(const float4*)&wsrc[(long)kk*COUT + o4];
        if(SPLIT==1){ v.x=to_tf32(v.x); v.y=to_tf32(v.y); v.z=to_tf32(v.z); v.w=to_tf32(v.w); }
        *(float4*)&ws[kk*LD + o4]=v;
      }
    }
    __syncthreads();
#pragma unroll
    for(int kc=0;kc<9;kc++){
      const int r=kc/3, kj=kc%3;
      const float* srch = (kj==1)? odh : evh;
      const float* srcl = (kj==1)? odl : evl;
      const int co = (kj==2)? 1:0;
      unsigned bh[8][2], bl[8][2];
#pragma unroll
      for(int f=0;f<8;f++){
        int i0=(tig*3+r)*LD + n0w + f*8 + gid + co;
        int i1=((tig+4)*3+r)*LD + n0w + f*8 + gid + co;
        bh[f][0]=__float_as_uint(srch[i0]);
        bh[f][1]=__float_as_uint(srch[i1]);
        if(SPLIT==3){
          bl[f][0]=__float_as_uint(srcl[i0]);
          bl[f][1]=__float_as_uint(srcl[i1]);
        }
      }
#pragma unroll
      for(int mf=0;mf<2;mf++){
        unsigned ah0,ah1,ah2,ah3,al0=0,al1=0,al2=0,al3=0;
        if(SPLIT==1){
          ah0=__float_as_uint(ws[(kc*8+tig)*LD + m0+mf*16+gid]);
          ah1=__float_as_uint(ws[(kc*8+tig)*LD + m0+mf*16+gid+8]);
          ah2=__float_as_uint(ws[(kc*8+tig+4)*LD + m0+mf*16+gid]);
          ah3=__float_as_uint(ws[(kc*8+tig+4)*LD + m0+mf*16+gid+8]);
        }else{
          float w0=ws[(kc*8+tig)*LD + m0+mf*16+gid];
          float w1=ws[(kc*8+tig)*LD + m0+mf*16+gid+8];
          float w2=ws[(kc*8+tig+4)*LD + m0+mf*16+gid];
          float w3=ws[(kc*8+tig+4)*LD + m0+mf*16+gid+8];
          float h0=to_tf32(w0),h1=to_tf32(w1),h2=to_tf32(w2),h3=to_tf32(w3);
          ah0=__float_as_uint(h0); ah1=__float_as_uint(h1);
          ah2=__float_as_uint(h2); ah3=__float_as_uint(h3);
          al0=__float_as_uint(to_tf32(w0-h0)); al1=__float_as_uint(to_tf32(w1-h1));
          al2=__float_as_uint(to_tf32(w2-h2)); al3=__float_as_uint(to_tf32(w3-h3));
        }
#pragma unroll
        for(int f=0;f<8;f++){
          mma_tf32(acc[mf][f], ah0,ah1,ah2,ah3, bh[f][0],bh[f][1]);
          if(SPLIT==3){
            mma_tf32(acc[mf][f], ah0,ah1,ah2,ah3, bl[f][0],bl[f][1]);
            mma_tf32(acc[mf][f], al0,al1,al2,al3, bh[f][0],bh[f][1]);
          }
        }
      }
    }
  }
#pragma unroll
  for(int mf=0;mf<2;mf++){
    int oA=o0+m0+mf*16+gid, oB=oA+8;
    float bA=bias[oA], bB=bias[oB];
#pragma unroll
    for(int f=0;f<8;f++){
      int jj=j0 + n0w + f*8 + tig*2;
      long baseA=(((long)n*COUT+oA)*HOUT+i)*WOUT + jj;
      long baseB=(((long)n*COUT+oB)*HOUT+i)*WOUT + jj;
      float2 rA, rB;
      rA.x=fmaxf(acc[mf][f][0]+bA,0.f); rA.y=fmaxf(acc[mf][f][1]+bA,0.f);
      rB.x=fmaxf(acc[mf][f][2]+bB,0.f); rB.y=fmaxf(acc[mf][f][3]+bB,0.f);
      *(float2*)&out[baseA]=rA;
      *(float2*)&out[baseB]=rB;
    }
  }
}

// ---------- tf32 mma transposed-conv bwd (S1, staging-side cvt) ----------
template<int CIN,int COUT,int HOUT,int WOUT,int NT>
__global__ void __launch_bounds__(256,2) k_cbmma(
    const float* __restrict__ dout, const float* __restrict__ WT,
    const float* __restrict__ act, float* __restrict__ din)
{
  constexpr int HIN=2*HOUT, WIN=2*WOUT;
  constexpr int LDW=CIN+8, LDD=NT/2+4, JL=NT/2+2;
  constexpr int NW_M=CIN/32;
  __shared__ float ws[72*LDW];
  __shared__ float dsA[8*LDD];
  __shared__ float dsB[8*LDD];
  const int n=blockIdx.z, x=blockIdx.y, y0=blockIdx.x*NT;
  const int tid=threadIdx.x, wid=tid>>5, lane=tid&31;
  const int gid=lane>>2, tig=lane&3;
  const int m0=(wid%NW_M)*32, n0=(wid/NW_M)*64;
  const bool xe=((x&1)==0);
  const int iA = xe ? (x>>1) : ((x-1)>>1);
  const int iB = (x>>1)-1;
  const bool hasB = xe && iB>=0;
  const int jb = y0/2 - 1;
  float acc_e[2][4][4], acc_o[2][4][4];
#pragma unroll
  for(int a=0;a<2;a++)
#pragma unroll
  for(int b=0;b<4;b++)
#pragma unroll
  for(int c=0;c<4;c++){acc_e[a][b][c]=0.f; acc_o[a][b][c]=0.f;}

  for(int o0=0;o0<COUT;o0+=8){
    __syncthreads();
    {
      const float* wsrc = WT + (long)(o0>>3)*72*CIN;
      for(int idx=tid; idx<72*(CIN/4); idx+=256){
        int r=idx/(CIN/4), c4=(idx%(CIN/4))*4;
        float4 v=*(const float4*)&wsrc[(long)r*CIN+c4];
        v.x=to_tf32(v.x); v.y=to_tf32(v.y); v.z=to_tf32(v.z); v.w=to_tf32(v.w);
        *(float4*)&ws[r*LDW+c4]=v;
      }
    }
    for(int idx=tid; idx<8*JL; idx+=256){
      int o=idx/JL, jl=idx%JL; int j=jb+jl;
      float a=0.f,bv=0.f;
      if(j>=0 && j<WOUT){
        long base=((long)n*COUT+o0+o)*HOUT;
        a = dout[(base+iA)*WOUT+j];
        if(hasB) bv = dout[(base+iB)*WOUT+j];
      }
      dsA[o*LDD+jl]=to_tf32(a); dsB[o*LDD+jl]=to_tf32(bv);
    }
    __syncthreads();

    auto proc = [&](const float* ds, const int tapBase){
      unsigned b1[4][2], b0[4][2];
#pragma unroll
      for(int f=0;f<4;f++){
        int cbase = n0/2 + f*8 + gid;
        b1[f][0]=__float_as_uint(ds[tig*LDD + cbase + 1]);
        b1[f][1]=__float_as_uint(ds[(tig+4)*LDD + cbase + 1]);
        b0[f][0]=__float_as_uint(ds[tig*LDD + cbase]);
        b0[f][1]=__float_as_uint(ds[(tig+4)*LDD + cbase]);
      }
#pragma unroll
      for(int kj=0;kj<3;kj++){
        const int tap=tapBase+kj;
#pragma unroll
        for(int mf=0;mf<2;mf++){
          unsigned a0=__float_as_uint(ws[(tap*8+tig)*LDW + m0+mf*16+gid]);
          unsigned a1=__float_as_uint(ws[(tap*8+tig)*LDW + m0+mf*16+gid+8]);
          unsigned a2=__float_as_uint(ws[(tap*8+tig+4)*LDW + m0+mf*16+gid]);
          unsigned a3=__float_as_uint(ws[(tap*8+tig+4)*LDW + m0+mf*16+gid+8]);
#pragma unroll
          for(int f=0;f<4;f++){
            float* c4 = (kj==1)? acc_o[mf][f] : acc_e[mf][f];
            const unsigned* bb = (kj==2)? b0[f] : b1[f];
            mma_tf32(c4, a0,a1,a2,a3, bb[0],bb[1]);
          }
        }
      }
    };
    proc(dsA, xe?0:3);
    if(hasB) proc(dsB, 6);
  }

#pragma unroll
  for(int mf=0;mf<2;mf++){
    int c0_=m0+mf*16+gid;
#pragma unroll
    for(int f=0;f<4;f++){
      int Y = y0 + n0 + 2*(f*8 + 2*tig);
      long b0i=(((long)n*CIN+c0_)*HIN+x)*WIN + Y;
      long b1i=(((long)n*CIN+c0_+8)*HIN+x)*WIN + Y;
      float2 m, r;
      m=*(const float2*)&act[b0i];
      r.x = m.x>0.f? acc_e[mf][f][0]:0.f; r.y = m.y>0.f? acc_o[mf][f][0]:0.f;
      *(float2*)&din[b0i]=r;
      m=*(const float2*)&act[b0i+2];
      r.x = m.x>0.f? acc_e[mf][f][1]:0.f; r.y = m.y>0.f? acc_o[mf][f][1]:0.f;
      *(float2*)&din[b0i+2]=r;
      m=*(const float2*)&act[b1i];
      r.x = m.x>0.f? acc_e[mf][f][2]:0.f; r.y = m.y>0.f? acc_o[mf][f][2]:0.f;
      *(float2*)&din[b1i]=r;
      m=*(const float2*)&act[b1i+2];
      r.x = m.x>0.f? acc_e[mf][f][3]:0.f; r.y = m.y>0.f? acc_o[mf][f][3]:0.f;
      *(float2*)&din[b1i+2]=r;
    }
  }
}

// ---------- conv1 data-grad -> |dx|, x-row-pair ----------
__global__ void __launch_bounds__(256) k_bwd1(
    const float* __restrict__ dz1, const float* __restrict__ W1,
    float* __restrict__ fam)
{
  __shared__ float ws[576];
  __shared__ float dsm[8*2*260];
  const int n=blockIdx.z, q=blockIdx.y, y0=blockIdx.x*512;
  const int tid=threadIdx.x;
  for(int idx=tid; idx<576; idx+=256) ws[idx]=W1[idx];
  const bool hasB=(q>0);
  const int jbase=y0/2-1;
  float aEE=0.f,aEO=0.f,aOE=0.f,aOO=0.f;
  for(int o0=0;o0<64;o0+=8){
    __syncthreads();
    for(int idx=tid; idx<8*2*260; idx+=256){
      int o=idx/520, rs=(idx/260)&1, jj=idx%260;
      int j=jbase+jj; int ir=rs? q-1 : q;
      float v=0.f;
      if(j>=0 && j<512 && (rs==0||hasB))
        v=dz1[(((long)n*64+o0+o)*64+ir)*512+j];
      dsm[idx]=v;
    }
    __syncthreads();
#pragma unroll
    for(int o=0;o<8;o++){
      const float* wb=&ws[(o0+o)*9];
      float vmA=dsm[(o*2)*260+tid], v0A=dsm[(o*2)*260+tid+1];
      aEE+=wb[0]*v0A+wb[2]*vmA; aEO+=wb[1]*v0A;
      if(hasB){
        float vmB=dsm[(o*2+1)*260+tid], v0B=dsm[(o*2+1)*260+tid+1];
        aEE+=wb[6]*v0B+wb[8]*vmB; aEO+=wb[7]*v0B;
      }
      aOE+=wb[3]*v0A+wb[5]*vmA; aOO+=wb[4]*v0A;
    }
  }
  long base=((long)n*128+2*q)*1024 + y0 + 2*tid;
  fam[base]=fabsf(aEE);      fam[base+1]=fabsf(aEO);
  fam[base+1024]=fabsf(aOE); fam[base+1025]=fabsf(aOO);
}

// ---------- att partial GEMM (S1, staging-side cvt) ----------
__global__ void __launch_bounds__(256) k_attp(
    const float* __restrict__ Wa, const float* __restrict__ feat,
    float* __restrict__ attp)
{
  constexpr int LDA=129, LDB=132;
  __shared__ float As[32*LDA];
  __shared__ float Bs[32*LDB];
  const int ks=blockIdx.x, b=blockIdx.y;
  const int tid=threadIdx.x, wid=tid>>5, lane=tid&31;
  const int gid=lane>>2, tig=lane&3;
  const int m0=(wid&3)*32, n0=(wid>>2)*64;
  const float* fb = feat + (long)b*524288;
  float acc[2][8][4];
#pragma unroll
  for(int a=0;a<2;a++)
#pragma unroll
  for(int bq=0;bq<8;bq++)
#pragma unroll
  for(int c=0;c<4;c++) acc[a][bq][c]=0.f;

  for(int k0=ks*512; k0<ks*512+512; k0+=32){
    __syncthreads();
    for(int idx=tid; idx<4096; idx+=256){
      int h=idx>>5, kk=idx&31;
      As[kk*LDA+h]=to_tf32(Wa[(long)h*4096+k0+kk]);
    }
    for(int idx=tid; idx<4096; idx+=256){
      int kk=idx>>7, t=idx&127;
      Bs[kk*LDB+t]=to_tf32(fb[(long)(k0+kk)*128+t]);
    }
    __syncthreads();
#pragma unroll
    for(int kc=0;kc<4;kc++){
      const int kb=kc*8;
      unsigned bh[8][2];
#pragma unroll
      for(int f=0;f<8;f++){
        bh[f][0]=__float_as_uint(Bs[(kb+tig)*LDB + n0+f*8+gid]);
        bh[f][1]=__float_as_uint(Bs[(kb+tig+4)*LDB + n0+f*8+gid]);
      }
#pragma unroll
      for(int mf=0;mf<2;mf++){
        unsigned a0=__float_as_uint(As[(kb+tig)*LDA + m0+mf*16+gid]);
        unsigned a1=__float_as_uint(As[(kb+tig)*LDA + m0+mf*16+gid+8]);
        unsigned a2=__float_as_uint(As[(kb+tig+4)*LDA + m0+mf*16+gid]);
        unsigned a3=__float_as_uint(As[(kb+tig+4)*LDA + m0+mf*16+gid+8]);
#pragma unroll
        for(int f=0;f<8;f++)
          mma_tf32(acc[mf][f], a0,a1,a2,a3, bh[f][0],bh[f][1]);
      }
    }
  }
#pragma unroll
  for(int mf=0;mf<2;mf++){
    int hA=m0+mf*16+gid, hB=hA+8;
#pragma unroll
    for(int f=0;f<8;f++){
      int t=n0+f*8+tig*2;
      float2 rA, rB;
      rA.x=acc[mf][f][0]; rA.y=acc[mf][f][1];
      rB.x=acc[mf][f][2]; rB.y=acc[mf][f][3];
      *(float2*)&attp[(long)ks*524288 + ((long)b*128+hA)*128+t]=rA;
      *(float2*)&attp[(long)ks*524288 + ((long)b*128+hB)*128+t]=rB;
    }
  }
}
__global__ void k_attf(const float* __restrict__ attp, const float* __restrict__ ba,
                       float* __restrict__ att)
{
  int i=blockIdx.x*256+threadIdx.x; if(i>=524288) return;
  int h=(i>>7)&127;
  float s=0.f;
#pragma unroll
  for(int ks=0;ks<8;ks++) s+=attp[(long)ks*524288+i];
  att[i]=tanhf(s+ba[h]);
}

// ---------- softmax ----------
__global__ void __launch_bounds__(128) k_salpha(
    const float* __restrict__ att, const float* __restrict__ va,
    float* __restrict__ alpha)
{
  __shared__ float vs[128], buf[128];
  const int b=blockIdx.x, t=threadIdx.x;
  vs[t]=va[t];
  __syncthreads();
  float s=0.f;
#pragma unroll 4
  for(int h=0;h<128;h++) s+=vs[h]*att[((long)b*128+h)*128+t];
  buf[t]=s; __syncthreads();
  for(int off=64;off;off>>=1){ if(t<off) buf[t]=fmaxf(buf[t],buf[t+off]); __syncthreads(); }
  float mx=buf[0]; __syncthreads();
  float e=expf(s-mx);
  buf[t]=e; __syncthreads();
  for(int off=64;off;off>>=1){ if(t<off) buf[t]+=buf[t+off]; __syncthreads(); }
  alpha[b*128+t]=e/buf[0];
}

// ---------- mu, m2 ----------
__global__ void k_mustats(const float* __restrict__ feat,
    const float* __restrict__ alpha, float* __restrict__ mu, float* __restrict__ m2)
{
  int w=(blockIdx.x*blockDim.x+threadIdx.x)>>5, lane=threadIdx.x&31;
  if(w>=131072) return;
  int b=w>>12;
  const float* fr=feat+(long)w*128;
  const float* ar=alpha+b*128;
  float s1=0.f,s2=0.f;
#pragma unroll
  for(int t=lane;t<128;t+=32){
    float a=ar[t], f=fr[t];
    s1+=a*f; s2+=a*f*f;
  }
  for(int o=16;o;o>>=1){ s1+=__shfl_down_sync(~0u,s1,o); s2+=__shfl_down_sync(~0u,s2,o); }
  if(!lane){ mu[w]=s1; m2[w]=s2; }
}

// ---------- gvec ----------
__global__ void k_gvec(const float* __restrict__ We,const float* __restrict__ Wc,
                       float* __restrict__ gvec)
{
  int w=(blockIdx.x*blockDim.x+threadIdx.x)>>5, lane=threadIdx.x&31;
  if(w>=8192) return;
  float s=0.f;
  for(int j=lane;j<256;j+=32) s+=We[(long)w*256+j]*(Wc[j*2+1]-Wc[j*2]);
  for(int o=16;o;o>>=1) s+=__shfl_down_sync(~0u,s,o);
  if(!lane) gvec[w]=s;
}

// ---------- dMu,dE2 ----------
__global__ void k_dcoef(const float* __restrict__ mu,const float* __restrict__ m2,
    const float* __restrict__ gvec, float* __restrict__ dMu,float* __restrict__ dE2)
{
  int i=blockIdx.x*256+threadIdx.x; if(i>=131072) return;
  int d=i&4095;
  float m=mu[i], v=m2[i]-m*m;
  float g2=gvec[4096+d];
  float dE=0.f, dM=gvec[d];
  if(v>1e-5f){ float sg=sqrtf(v); dE=0.5f*g2/sg; dM-=g2*m/sg; }
  dMu[i]=dM; dE2[i]=dE;
}

// ---------- dalpha ----------
__global__ void __launch_bounds__(128) k_dalp(
    const float* __restrict__ feat,const float* __restrict__ dMu,
    const float* __restrict__ dE2,float* __restrict__ part)
{
  const int ks=blockIdx.x, b=blockIdx.y, t=threadIdx.x;
  const float* fb=feat+(long)b*524288;
  const float* dm=dMu+b*4096; const float* de=dE2+b*4096;
  float acc=0.f;
  int d0=ks*512;
#pragma unroll 4
  for(int d=d0;d<d0+512;d++){
    float f=fb[(long)d*128+t];
    acc+=dm[d]*f+de[d]*f*f;
  }
  part[(ks*32+b)*128+t]=acc;
}
__global__ void __launch_bounds__(128) k_dalf(
    const float* __restrict__ part,const float* __restrict__ alpha,
    float* __restrict__ ds)
{
  const int b=blockIdx.x, t=threadIdx.x;
  float acc=0.f;
#pragma unroll
  for(int ks=0;ks<8;ks++) acc+=part[(ks*32+b)*128+t];
  __shared__ float buf[128];
  float a=alpha[b*128+t];
  buf[t]=a*acc; __syncthreads();
  for(int off=64;off;off>>=1){ if(t<off) buf[t]+=buf[t+off]; __syncthreads(); }
  ds[b*128+t]=a*(acc-buf[0]);
}

// ---------- dfeat (S1, dz computed in-staging) + fused epilogue ----------
__global__ void __launch_bounds__(256) k_dfeat(
    const float* __restrict__ Wa, const float* __restrict__ att,
    const float* __restrict__ va, const float* __restrict__ ds,
    const float* __restrict__ feat, const float* __restrict__ alpha,
    const float* __restrict__ dMu, const float* __restrict__ dE2,
    float* __restrict__ dout3)
{
  constexpr int LDA=132, LDB=132;
  __shared__ float As[32*LDA];
  __shared__ float Bs[32*LDB];
  __shared__ float al[128], vs[128], dsv[128];
  const int d0=blockIdx.x*128, b=blockIdx.y;
  const int tid=threadIdx.x, wid=tid>>5, lane=tid&31;
  const int gid=lane>>2, tig=lane&3;
  const int m0=(wid&3)*32, n0=(wid>>2)*64;
  if(tid<128){
    al[tid]=alpha[b*128+tid];
    vs[tid]=va[tid];
    dsv[tid]=ds[b*128+tid];
  }
  float acc[2][8][4];
#pragma unroll
  for(int a=0;a<2;a++)
#pragma unroll
  for(int bq=0;bq<8;bq++)
#pragma unroll
  for(int c=0;c<4;c++) acc[a][bq][c]=0.f;

  for(int k0=0;k0<128;k0+=32){
    __syncthreads();
    for(int idx=tid; idx<4096; idx+=256){
      int kk=idx>>7, dd=idx&127;
      As[kk*LDA+dd]=to_tf32(Wa[(long)(k0+kk)*4096+d0+dd]);
    }
    for(int idx=tid; idx<4096; idx+=256){
      int kk=idx>>7, t=idx&127;
      int h=k0+kk;
      float a=att[((long)b*128+h)*128+t];
      float dzv=vs[h]*dsv[t]*(1.f-a*a);
      Bs[kk*LDB+t]=to_tf32(dzv);
    }
    __syncthreads();
#pragma unroll
    for(int kc=0;kc<4;kc++){
      const int kb=kc*8;
      unsigned bh[8][2];
#pragma unroll
      for(int f=0;f<8;f++){
        bh[f][0]=__float_as_uint(Bs[(kb+tig)*LDB + n0+f*8+gid]);
        bh[f][1]=__float_as_uint(Bs[(kb+tig+4)*LDB + n0+f*8+gid]);
      }
#pragma unroll
      for(int mf=0;mf<2;mf++){
        unsigned a0=__float_as_uint(As[(kb+tig)*LDA + m0+mf*16+gid]);
        unsigned a1=__float_as_uint(As[(kb+tig)*LDA + m0+mf*16+gid+8]);
        unsigned a2=__float_as_uint(As[(kb+tig+4)*LDA + m0+mf*16+gid]);
        unsigned a3=__float_as_uint(As[(kb+tig+4)*LDA + m0+mf*16+gid+8]);
#pragma unroll
        for(int f=0;f<8;f++)
          mma_tf32(acc[mf][f], a0,a1,a2,a3, bh[f][0],bh[f][1]);
      }
    }
  }
#pragma unroll
  for(int mf=0;mf<2;mf++){
    int dA=d0+m0+mf*16+gid, dB=dA+8;
    float dmA=dMu[(long)b*4096+dA], deA=dE2[(long)b*4096+dA];
    float dmB=dMu[(long)b*4096+dB], deB=dE2[(long)b*4096+dB];
#pragma unroll
    for(int f=0;f<8;f++){
      int t=n0+f*8+tig*2;
      long fiA=((long)b*4096+dA)*128+t;
      long fiB=((long)b*4096+dB)*128+t;
      float2 fvA=*(const float2*)&feat[fiA];
      float2 fvB=*(const float2*)&feat[fiB];
      float2 rA, rB;
      rA.x = fvA.x>0.f? (acc[mf][f][0]+al[t]*(dmA+2.f*deA*fvA.x)) : 0.f;
      rA.y = fvA.y>0.f? (acc[mf][f][1]+al[t+1]*(dmA+2.f*deA*fvA.y)) : 0.f;
      rB.x = fvB.x>0.f? (acc[mf][f][2]+al[t]*(dmB+2.f*deB*fvB.x)) : 0.f;
      rB.y = fvB.y>0.f? (acc[mf][f][3]+al[t+1]*(dmB+2.f*deB*fvB.y)) : 0.f;
      *(float2*)&dout3[fiA]=rA;
      *(float2*)&dout3[fiB]=rB;
    }
  }
}

// ---------- row/col stats ----------
__global__ void k_rowstats(const float* __restrict__ fam,const float* __restrict__ x,
    float* __restrict__ cm,float* __restrict__ meanT)
{
  int w=(blockIdx.x*blockDim.x+threadIdx.x)>>5, lane=threadIdx.x&31;
  if(w>=4096) return;
  const float* fr=fam+(long)w*1024; const float* xr=x+(long)w*1024;
  float m=-1e30f, s=0.f;
  for(int t=lane;t<1024;t+=32){ m=fmaxf(m,fr[t]); s+=xr[t]; }
  for(int o=16;o;o>>=1){ m=fmaxf(m,__shfl_down_sync(~0u,m,o)); s+=__shfl_down_sync(~0u,s,o); }
  if(!lane){ cm[w]=m; meanT[w]=s*(1.f/1024.f); }
}
__global__ void k_colstats(const float* __restrict__ fam,const float* __restrict__ x,
    float* __restrict__ tm,float* __restrict__ meanF)
{
  int i=blockIdx.x*256+threadIdx.x; if(i>=32768) return;
  int b=i>>10, t=i&1023;
  const float* fb=fam+(long)b*131072+t; const float* xb=x+(long)b*131072+t;
  float m=-1e30f, s=0.f;
#pragma unroll 4
  for(int f=0;f<128;f++){ m=fmaxf(m,fb[f*1024]); s+=xb[f*1024]; }
  tm[i]=m; meanF[i]=s*(1.f/128.f);
}

// ---------- bitonic argsort ----------
template<int N>
__global__ void k_sort(const float* __restrict__ vals, int* __restrict__ idxout)
{
  __shared__ unsigned long long key[N];
  const int b=blockIdx.x, tid=threadIdx.x, TH=N/2;
  for(int i=tid;i<N;i+=TH){
    unsigned u=__float_as_uint(vals[b*N+i]);
    u = (u&0x80000000u)? ~u : (u|0x80000000u);
    key[i]=((unsigned long long)(~u)<<32)|(unsigned)i;
  }
  __syncthreads();
  for(int k=2;k<=N;k<<=1)
    for(int j=k>>1;j;j>>=1){
      for(int i=tid;i<N;i+=TH){
        int ixj=i^j;
        if(ixj>i){
          bool up=((i&k)==0);
          unsigned long long a=key[i],c=key[ixj];
          if((a>c)==up){ key[i]=c; key[ixj]=a; }
        }
      }
      __syncthreads();
    }
  for(int i=tid;i<128;i+=TH) idxout[b*128+i]=(int)(key[i]&0xFFFFFFFFu);
}

// ---------- RFM scan (parallel init) + mask prefixes ----------
__global__ void k_rfm(const int* __restrict__ sc,const int* __restrict__ st,
    const int* __restrict__ mask_t,const int* __restrict__ s_t,
    const int* __restrict__ is_train,int* __restrict__ rstep,int* __restrict__ cstep,
    int* __restrict__ rowp,int* __restrict__ colp)
{
  const int b=blockIdx.x, t=threadIdx.x;
  int* rs=rstep+b*128; int* cs=cstep+b*1024;
  rs[t]=-1;
  for(int i=t;i<1024;i+=128) cs[i]=-1;
  __syncthreads();
  if(t==0){
    bool train = !(is_train && is_train[0]==0);
    if(train){
      int cnt=0;
      for(int s=0;s<128 && cnt<3;s++){
        int pc=sc[b*128+s], pt=st[b*128+s];
        if(rs[pc]!=-1||cs[pt]!=-1) continue;
        int mt=mask_t[b*128+s], ss=s_t[b*128+s];
        rs[pc]=s;
        int l=pt-ss; if(l<0)l=0;
        int r=pt+mt-ss; if(r>1024)r=1024;
        for(int tt=l;tt<r;tt++) cs[tt]=s;
        cnt++;
      }
    }
    // prefixes over mask indicators
    int acc=0;
    rowp[b*129]=0;
    for(int i=0;i<128;i++){ acc += (rs[i]>=0); rowp[b*129+i+1]=acc; }
    acc=0;
    colp[b*1025]=0;
    for(int i=0;i<1024;i++){ acc += (cs[i]>=0); colp[b*1025+i+1]=acc; }
  }
}

// ---------- apply mask ----------
__global__ void k_apply(const float* __restrict__ x,const int* __restrict__ rstep,
    const int* __restrict__ cstep,const float* __restrict__ meanT,
    const float* __restrict__ meanF,float* __restrict__ xm)
{
  long i=(long)blockIdx.x*256+threadIdx.x; if(i>=4194304) return;
  int t=(int)(i&1023); int f=(int)((i>>10)&127); int b=(int)(i>>17);
  int rs=rstep[b*128+f], cs=cstep[b*1024+t];
  float v;
  if(rs<0&&cs<0) v=x[i];
  else v=(cs>=rs)? meanT[b*128+f] : meanF[b*1024+t];
  xm[i]=v;
}

// ---------- emb head ----------
__global__ void k_cat(const float* __restrict__ mu,const float* __restrict__ m2,
                      float* __restrict__ cat)
{
  int i=blockIdx.x*256+threadIdx.x; if(i>=131072) return;
  int b=i>>12, d=i&4095;
  float m=mu[i];
  cat[(long)b*8192+d]=m;
  cat[(long)b*8192+4096+d]=sqrtf(fmaxf(m2[i]-m*m,1e-5f));
}
__global__ void __launch_bounds__(256) k_embp(
    const float* __restrict__ cat,const float* __restrict__ We,
    float* __restrict__ part)
{
  __shared__ float cs[32][64];
  const int ks=blockIdx.x, j=threadIdx.x;
  for(int idx=j; idx<32*64; idx+=256){
    int b=idx>>6, ii=idx&63;
    cs[b][ii]=cat[(long)b*8192 + ks*64 + ii];
  }
  __syncthreads();
  float acc[32];
#pragma unroll
  for(int b=0;b<32;b++) acc[b]=0.f;
  for(int ii=0;ii<64;ii++){
    float w=We[((long)ks*64+ii)*256+j];
#pragma unroll
    for(int b=0;b<32;b++) acc[b]+=cs[b][ii]*w;
  }
#pragma unroll
  for(int b=0;b<32;b++) part[((long)ks*32+b)*256+j]=acc[b];
}
__global__ void __launch_bounds__(256) k_embf(
    const float* __restrict__ part,const float* __restrict__ be,
    const float* __restrict__ Wc,const float* __restrict__ bc,
    float* __restrict__ out)
{
  const int b=blockIdx.x, j=threadIdx.x;
  float s=be[j];
  for(int ks=0;ks<128;ks++) s+=part[((long)ks*32+b)*256+j];
  __shared__ float es[256];
  es[j]=s; __syncthreads();
  if(j<2){
    float acc=bc[j];
    for(int q=0;q<256;q++) acc+=es[q]*Wc[q*2+j];
    out[b*2+j]=acc;
  }
}

// ---------- host ----------
static void run_tail(const float* h3,const float* Wa,const float* ba,const float* va,
                     float* attp,float* att,float* alpha,float* mu,float* m2)
{
  k_attp<<<dim3(8,32),256>>>(Wa,h3,attp);
  k_attf<<<2048,256>>>(attp,ba,att);
  k_salpha<<<32,128>>>(att,va,alpha);
  k_mustats<<<16384,256>>>(h3,alpha,mu,m2);
}

extern "C" void kernel_launch(void* const* d_in,const int* in_sizes,int n_in,
                              void* d_out,int out_size)
{
  const float* x =(const float*)d_in[0];
  const float* W1=(const float*)d_in[1]; const float* b1=(const float*)d_in[2];
  const float* W2=(const float*)d_in[3]; const float* b2=(const float*)d_in[4];
  const float* W3=(const float*)d_in[5]; const float* b3=(const float*)d_in[6];
  const float* Wa=(const float*)d_in[7]; const float* ba=(const float*)d_in[8];
  const float* va=(const float*)d_in[9];
  const float* We=(const float*)d_in[10]; const float* be=(const float*)d_in[11];
  const float* Wc=(const float*)d_in[12]; const float* bc=(const float*)d_in[13];
  const int* mask_t=(const int*)d_in[14]; const int* s_t=(const int*)d_in[15];
  const int* is_train = (n_in>16)? (const int*)d_in[16] : nullptr;
  float* out=(float*)d_out;

  float *h1,*h2,*h3,*d1,*d2,*d3,*fam,*xm,*att,*attp,*alpha,*ds,*dap,*mu,*m2,*dMu,*dE2,*gvec;
  float *cat,*ep,*cm,*tm,*meanT,*meanF,*wtf2,*wtb2,*wtf3,*wtb3;
  int *sc,*st,*rstep,*cstep,*rowp,*colp;
  cudaGetSymbolAddress((void**)&h1,g_h1);   cudaGetSymbolAddress((void**)&h2,g_h2);
  cudaGetSymbolAddress((void**)&h3,g_h3);   cudaGetSymbolAddress((void**)&d1,g_d1);
  cudaGetSymbolAddress((void**)&d2,g_d2);   cudaGetSymbolAddress((void**)&d3,g_d3);
  cudaGetSymbolAddress((void**)&fam,g_fam); cudaGetSymbolAddress((void**)&xm,g_xm);
  cudaGetSymbolAddress((void**)&att,g_att); cudaGetSymbolAddress((void**)&attp,g_attp);
  cudaGetSymbolAddress((void**)&alpha,g_alpha); cudaGetSymbolAddress((void**)&ds,g_dsb);
  cudaGetSymbolAddress((void**)&dap,g_dap);
  cudaGetSymbolAddress((void**)&mu,g_mu);   cudaGetSymbolAddress((void**)&m2,g_m2);
  cudaGetSymbolAddress((void**)&dMu,g_dMu); cudaGetSymbolAddress((void**)&dE2,g_dE2);
  cudaGetSymbolAddress((void**)&gvec,g_gvec);
  cudaGetSymbolAddress((void**)&cat,g_cat); cudaGetSymbolAddress((void**)&ep,g_ep);
  cudaGetSymbolAddress((void**)&cm,g_cm);   cudaGetSymbolAddress((void**)&tm,g_tm);
  cudaGetSymbolAddress((void**)&meanT,g_meanT); cudaGetSymbolAddress((void**)&meanF,g_meanF);
  cudaGetSymbolAddress((void**)&sc,g_sc);   cudaGetSymbolAddress((void**)&st,g_st);
  cudaGetSymbolAddress((void**)&rstep,g_rstep); cudaGetSymbolAddress((void**)&cstep,g_cstep);
  cudaGetSymbolAddress((void**)&rowp,g_rowp);   cudaGetSymbolAddress((void**)&colp,g_colp);
  cudaGetSymbolAddress((void**)&wtf2,g_wtf2); cudaGetSymbolAddress((void**)&wtb2,g_wtb2);
  cudaGetSymbolAddress((void**)&wtf3,g_wtf3); cudaGetSymbolAddress((void**)&wtb3,g_wtb3);

  const int SMEM1 = 120*136*4;
  const int SMEM3 = 168*136*4;
  cudaFuncSetAttribute(k_cmma<64,128,64,512,1>,  cudaFuncAttributeMaxDynamicSharedMemorySize, SMEM1);
  cudaFuncSetAttribute(k_cmma<64,128,64,512,3>,  cudaFuncAttributeMaxDynamicSharedMemorySize, SMEM3);
  cudaFuncSetAttribute(k_cmma<128,256,32,256,1>, cudaFuncAttributeMaxDynamicSharedMemorySize, SMEM1);
  cudaFuncSetAttribute(k_cmma<128,256,32,256,3>, cudaFuncAttributeMaxDynamicSharedMemorySize, SMEM3);

  // prep
  k_wt<<<288,256>>>(W2,wtf2,wtb2,64,128);
  k_wt<<<1152,256>>>(W3,wtf3,wtb3,128,256);
  k_gvec<<<1024,256>>>(We,Wc,gvec);
  // pass 1: forward convs 3xTF32 (argsort-critical)
  k_conv1<<<dim3(4,64,32),256>>>(x,W1,b1,h1,nullptr,nullptr);
  k_cmma<64,128,64,512,3><<<dim3(2,32,32),256,SMEM3>>>(h1,wtf2,b2,h2);
  k_cmma<128,256,32,256,3><<<dim3(2,16,32),256,SMEM3>>>(h2,wtf3,b3,h3);
  run_tail(h3,Wa,ba,va,attp,att,alpha,mu,m2);
  // backward to input: single-tf32
  k_dcoef<<<512,256>>>(mu,m2,gvec,dMu,dE2);
  k_dalp<<<dim3(8,32),128>>>(h3,dMu,dE2,dap);
  k_dalf<<<32,128>>>(dap,alpha,ds);
  k_dfeat<<<dim3(32,32),256>>>(Wa,att,va,ds,h3,alpha,dMu,dE2,d3);
  k_cbmma<128,256,16,128,128><<<dim3(2,32,32),256>>>(d3,wtb3,h2,d2);
  k_cbmma<64,128,32,256,256><<<dim3(2,64,32),256>>>(d2,wtb2,h1,d1);
  k_bwd1<<<dim3(2,64,32),256>>>(d1,W1,fam);
  // masking
  k_rowstats<<<512,256>>>(fam,x,cm,meanT);
  k_colstats<<<128,256>>>(fam,x,tm,meanF);
  k_sort<128><<<32,64>>>(cm,sc);
  k_sort<1024><<<32,512>>>(tm,st);
  k_rfm<<<32,128>>>(sc,st,mask_t,s_t,is_train,rstep,cstep,rowp,colp);
  k_apply<<<16384,256>>>(x,rstep,cstep,meanT,meanF,xm);
  // pass 2 (single tf32); conv1 updates h1 in place, skipping unmasked tiles
  k_conv1<<<dim3(4,64,32),256>>>(xm,W1,b1,h1,rowp,colp);
  k_cmma<64,128,64,512,1><<<dim3(2,32,32),256,SMEM1>>>(h1,wtf2,b2,h2);
  k_cmma<128,256,32,256,1><<<dim3(2,16,32),256,SMEM1>>>(h2,wtf3,b3,h3);
  run_tail(h3,Wa,ba,va,attp,att,alpha,mu,m2);
  k_cat<<<512,256>>>(mu,m2,cat);
  k_embp<<<128,256>>>(cat,We,ep);
  k_embf<<<32,256>>>(ep,be,Wc,bc,out);
}

// round 15
// speedup vs baseline: 1.0117x; 1.0117x over previous
#include <cuda_runtime.h>
#include <math.h>

// ---------- static scratch ----------
__device__ float g_h1[67108864];
__device__ float g_h2[33554432];
__device__ float g_h3[16777216];
__device__ float g_d1[67108864];
__device__ float g_d2[33554432];
__device__ float g_d3[16777216];
__device__ float g_fam[4194304];
__device__ float g_xm[4194304];
__device__ float g_att[524288];
__device__ float g_attp[4194304];
__device__ float g_alpha[4096];
__device__ float g_dsb[4096];
__device__ float g_dap[32768];
__device__ float g_mu[131072];
__device__ float g_m2[131072];
__device__ float g_dMu[131072];
__device__ float g_dE2[131072];
__device__ float g_gvec[8192];
__device__ float g_cat[262144];
__device__ float g_ep[1048576];
__device__ float g_cm[4096];
__device__ float g_tm[32768];
__device__ float g_meanT[4096];
__device__ float g_meanF[32768];
__device__ int   g_sc[4096];
__device__ int   g_st[4096];
__device__ int   g_rstep[4096];
__device__ int   g_cstep[32768];
__device__ int   g_rowp[4128];
__device__ int   g_colp[32800];
__device__ float g_wtf2[73728];
__device__ float g_wtb2[73728];
__device__ float g_wtf3[294912];
__device__ float g_wtb3[294912];

// ---------- weight transposes ----------
__global__ void k_wt(const float* __restrict__ W, float* __restrict__ WTf,
                     float* __restrict__ WTb, int CIN, int COUT)
{
  int idx=blockIdx.x*256+threadIdx.x;
  int tot=CIN*COUT*9; if(idx>=tot) return;
  int k=idx%9, c=(idx/9)%CIN, o=idx/(9*CIN);
  float v=W[idx];
  int rf=(c>>3)*72 + k*8 + (c&7);
  WTf[(long)rf*COUT+o]=v;
  int rb=(o>>3)*72 + k*8 + (o&7);
  WTb[(long)rb*CIN+c]=v;
}

// ---------- conv1 fwd (R12 shape + optional tile-skip) ----------
__global__ void __launch_bounds__(256) k_conv1(
    const float* __restrict__ in, const float* __restrict__ W,
    const float* __restrict__ bias, float* __restrict__ out,
    const int* __restrict__ rowp, const int* __restrict__ colp)
{
  __shared__ __align__(16) float ins[3][132];
  __shared__ __align__(16) float ws[9][64];
  __shared__ float bs[64];
  const int n=blockIdx.z, i=blockIdx.y, j0=blockIdx.x*64;
  if(rowp){
    int r0=2*i, r1=2*i+3; if(r1>128) r1=128;
    int c0=2*j0, c1=2*j0+130; if(c1>1024) c1=1024;
    if(rowp[n*129+r1]==rowp[n*129+r0] && colp[n*1025+c1]==colp[n*1025+c0]) return;
  }
  const int tid=threadIdx.x, jt=tid&15, og=tid>>4;
  for(int idx=tid; idx<576; idx+=256){
    int o=idx/9, k=idx%9;
    ws[k][o]=W[idx];
  }
  if(tid<64) bs[tid]=bias[tid];
  for(int idx=tid; idx<3*130; idx+=256){
    int r=idx/130, col=idx%130;
    int gx=2*i+r, gy=2*j0+col;
    float v=0.f;
    if(gx<128 && gy<1024) v=in[((long)n*128+gx)*1024+gy];
    ins[r][col]=v;
  }
  __syncthreads();
  float acc[4][4];
#pragma unroll
  for(int o=0;o<4;o++)
#pragma unroll
  for(int e=0;e<4;e++) acc[o][e]=0.f;
#pragma unroll
  for(int r=0;r<3;r++){
    float v[9];
    *(float4*)v     = *(float4*)&ins[r][8*jt];
    *(float4*)(v+4) = *(float4*)&ins[r][8*jt+4];
    v[8]            = ins[r][8*jt+8];
#pragma unroll
    for(int kj=0;kj<3;kj++){
      float w[4];
      *(float4*)w = *(float4*)&ws[r*3+kj][og*4];
#pragma unroll
      for(int oo=0;oo<4;oo++)
#pragma unroll
      for(int e=0;e<4;e++)
        acc[oo][e]+=w[oo]*v[2*e+kj];
    }
  }
#pragma unroll
  for(int oo=0;oo<4;oo++){
    int o=og*4+oo;
    float bb=bs[o];
    float4 r;
    r.x=fmaxf(acc[oo][0]+bb,0.f); r.y=fmaxf(acc[oo][1]+bb,0.f);
    r.z=fmaxf(acc[oo][2]+bb,0.f); r.w=fmaxf(acc[oo][3]+bb,0.f);
    *(float4*)&out[(((long)n*64+o)*64+i)*512 + j0 + 4*jt]=r;
  }
}

// ---------- tf32 helpers ----------
__device__ __forceinline__ float to_tf32(float v){
  unsigned r; asm("cvt.rna.tf32.f32 %0, %1;" : "=r"(r) : "f"(v));
  return __uint_as_float(r);
}
__device__ __forceinline__ void mma_tf32(float* c4,
    unsigned a0,unsigned a1,unsigned a2,unsigned a3,unsigned b0,unsigned b1){
  asm volatile(
    "mma.sync.aligned.m16n8k8.row.col.f32.tf32.tf32.f32 "
    "{%0,%1,%2,%3},{%4,%5,%6,%7},{%8,%9},{%0,%1,%2,%3};"
    : "+f"(c4[0]),"+f"(c4[1]),"+f"(c4[2]),"+f"(c4[3])
    : "r"(a0),"r"(a1),"r"(a2),"r"(a3),"r"(b0),"r"(b1));
}

// ---------- tf32 mma conv fwd; staging-side cvt ----------
template<int CIN,int COUT,int HIN,int WIN,int SPLIT>
__global__ void __launch_bounds__(256,2) k_cmma(
    const float* __restrict__ in, const float* __restrict__ WT,
    const float* __restrict__ bias, float* __restrict__ out)
{
  constexpr int HOUT=HIN/2, WOUT=WIN/2;
  constexpr int NJT=WOUT/128;
  constexpr int LD=136;
  constexpr int WOFF=(SPLIT==3)?96:48;
  extern __shared__ float sm[];
  float* evh = sm;
  float* odh = sm + 24*LD;
  float* evl = sm + 48*LD;
  float* odl = sm + 72*LD;
  float* ws  = sm + WOFF*LD;
  const int n=blockIdx.z, i=blockIdx.y;
  const int jt_=blockIdx.x%NJT, ot=blockIdx.x/NJT;
  const int j0=jt_*128, o0=ot*128;
  const int tid=threadIdx.x, wid=tid>>5, lane=tid&31;
  const int gid=lane>>2, tig=lane&3;
  const int m0=(wid&3)*32, n0w=(wid>>2)*64;
  float acc[2][8][4];
#pragma unroll
  for(int a=0;a<2;a++)
#pragma unroll
  for(int b=0;b<8;b++)
#pragma unroll
  for(int c=0;c<4;c++) acc[a][b][c]=0.f;

  for(int c0=0;c0<CIN;c0+=8){
    __syncthreads();
    for(int idx=tid; idx<8*3*129; idx+=256){
      int c=idx/387, rem=idx%387, r=rem/129, p=rem%129;
      int gx=2*i+r, gy=2*j0+2*p;
      float a=0.f,bv=0.f;
      if(gx<HIN && gy<WIN){
        const float2 s=*(const float2*)&in[(((long)n*CIN+c0+c)*HIN+gx)*WIN+gy];
        a=s.x; bv=s.y;
      }
      float ah=to_tf32(a), bh=to_tf32(bv);
      evh[(c*3+r)*LD+p]=ah;
      odh[(c*3+r)*LD+p]=bh;
      if(SPLIT==3){
        evl[(c*3+r)*LD+p]=to_tf32(a-ah);
        odl[(c*3+r)*LD+p]=to_tf32(bv-bh);
      }
    }
    {
      const float* wsrc = WT + (long)(c0>>3)*72*COUT + o0;
      for(int idx=tid; idx<72*32; idx+=256){
        int kk=idx>>5, o4=(idx&31)*4;
        float4 v=*(const float4*)&wsrc[(long)kk*COUT + o4];
        if(SPLIT==1){ v.x=to_tf32(v.x); v.y=to_tf32(v.y); v.z=to_tf32(v.z); v.w=to_tf32(v.w); }
        *(float4*)&ws[kk*LD + o4]=v;
      }
    }
    __syncthreads();
#pragma unroll
    for(int kc=0;kc<9;kc++){
      const int r=kc/3, kj=kc%3;
      const float* srch = (kj==1)? odh : evh;
      const float* srcl = (kj==1)? odl : evl;
      const int co = (kj==2)? 1:0;
      unsigned bh[8][2], bl[8][2];
#pragma unroll
      for(int f=0;f<8;f++){
        int i0=(tig*3+r)*LD + n0w + f*8 + gid + co;
        int i1=((tig+4)*3+r)*LD + n0w + f*8 + gid + co;
        bh[f][0]=__float_as_uint(srch[i0]);
        bh[f][1]=__float_as_uint(srch[i1]);
        if(SPLIT==3){
          bl[f][0]=__float_as_uint(srcl[i0]);
          bl[f][1]=__float_as_uint(srcl[i1]);
        }
      }
#pragma unroll
      for(int mf=0;mf<2;mf++){
        unsigned ah0,ah1,ah2,ah3,al0=0,al1=0,al2=0,al3=0;
        if(SPLIT==1){
          ah0=__float_as_uint(ws[(kc*8+tig)*LD + m0+mf*16+gid]);
          ah1=__float_as_uint(ws[(kc*8+tig)*LD + m0+mf*16+gid+8]);
          ah2=__float_as_uint(ws[(kc*8+tig+4)*LD + m0+mf*16+gid]);
          ah3=__float_as_uint(ws[(kc*8+tig+4)*LD + m0+mf*16+gid+8]);
        }else{
          float w0=ws[(kc*8+tig)*LD + m0+mf*16+gid];
          float w1=ws[(kc*8+tig)*LD + m0+mf*16+gid+8];
          float w2=ws[(kc*8+tig+4)*LD + m0+mf*16+gid];
          float w3=ws[(kc*8+tig+4)*LD + m0+mf*16+gid+8];
          float h0=to_tf32(w0),h1=to_tf32(w1),h2=to_tf32(w2),h3=to_tf32(w3);
          ah0=__float_as_uint(h0); ah1=__float_as_uint(h1);
          ah2=__float_as_uint(h2); ah3=__float_as_uint(h3);
          al0=__float_as_uint(to_tf32(w0-h0)); al1=__float_as_uint(to_tf32(w1-h1));
          al2=__float_as_uint(to_tf32(w2-h2)); al3=__float_as_uint(to_tf32(w3-h3));
        }
#pragma unroll
        for(int f=0;f<8;f++){
          mma_tf32(acc[mf][f], ah0,ah1,ah2,ah3, bh[f][0],bh[f][1]);
          if(SPLIT==3){
            mma_tf32(acc[mf][f], ah0,ah1,ah2,ah3, bl[f][0],bl[f][1]);
            mma_tf32(acc[mf][f], al0,al1,al2,al3, bh[f][0],bh[f][1]);
          }
        }
      }
    }
  }
#pragma unroll
  for(int mf=0;mf<2;mf++){
    int oA=o0+m0+mf*16+gid, oB=oA+8;
    float bA=bias[oA], bB=bias[oB];
#pragma unroll
    for(int f=0;f<8;f++){
      int jj=j0 + n0w + f*8 + tig*2;
      long baseA=(((long)n*COUT+oA)*HOUT+i)*WOUT + jj;
      long baseB=(((long)n*COUT+oB)*HOUT+i)*WOUT + jj;
      float2 rA, rB;
      rA.x=fmaxf(acc[mf][f][0]+bA,0.f); rA.y=fmaxf(acc[mf][f][1]+bA,0.f);
      rB.x=fmaxf(acc[mf][f][2]+bB,0.f); rB.y=fmaxf(acc[mf][f][3]+bB,0.f);
      *(float2*)&out[baseA]=rA;
      *(float2*)&out[baseB]=rB;
    }
  }
}

// ---------- tf32 mma transposed-conv bwd (S1, staging-side cvt) ----------
template<int CIN,int COUT,int HOUT,int WOUT,int NT>
__global__ void __launch_bounds__(256,2) k_cbmma(
    const float* __restrict__ dout, const float* __restrict__ WT,
    const float* __restrict__ act, float* __restrict__ din)
{
  constexpr int HIN=2*HOUT, WIN=2*WOUT;
  constexpr int LDW=CIN+8, LDD=NT/2+4, JL=NT/2+2;
  constexpr int NW_M=CIN/32;
  __shared__ float ws[72*LDW];
  __shared__ float dsA[8*LDD];
  __shared__ float dsB[8*LDD];
  const int n=blockIdx.z, x=blockIdx.y, y0=blockIdx.x*NT;
  const int tid=threadIdx.x, wid=tid>>5, lane=tid&31;
  const int gid=lane>>2, tig=lane&3;
  const int m0=(wid%NW_M)*32, n0=(wid/NW_M)*64;
  const bool xe=((x&1)==0);
  const int iA = xe ? (x>>1) : ((x-1)>>1);
  const int iB = (x>>1)-1;
  const bool hasB = xe && iB>=0;
  const int jb = y0/2 - 1;
  float acc_e[2][4][4], acc_o[2][4][4];
#pragma unroll
  for(int a=0;a<2;a++)
#pragma unroll
  for(int b=0;b<4;b++)
#pragma unroll
  for(int c=0;c<4;c++){acc_e[a][b][c]=0.f; acc_o[a][b][c]=0.f;}

  for(int o0=0;o0<COUT;o0+=8){
    __syncthreads();
    {
      const float* wsrc = WT + (long)(o0>>3)*72*CIN;
      for(int idx=tid; idx<72*(CIN/4); idx+=256){
        int r=idx/(CIN/4), c4=(idx%(CIN/4))*4;
        float4 v=*(const float4*)&wsrc[(long)r*CIN+c4];
        v.x=to_tf32(v.x); v.y=to_tf32(v.y); v.z=to_tf32(v.z); v.w=to_tf32(v.w);
        *(float4*)&ws[r*LDW+c4]=v;
      }
    }
    for(int idx=tid; idx<8*JL; idx+=256){
      int o=idx/JL, jl=idx%JL; int j=jb+jl;
      float a=0.f,bv=0.f;
      if(j>=0 && j<WOUT){
        long base=((long)n*COUT+o0+o)*HOUT;
        a = dout[(base+iA)*WOUT+j];
        if(hasB) bv = dout[(base+iB)*WOUT+j];
      }
      dsA[o*LDD+jl]=to_tf32(a); dsB[o*LDD+jl]=to_tf32(bv);
    }
    __syncthreads();

    auto proc = [&](const float* ds, const int tapBase){
      unsigned b1[4][2], b0[4][2];
#pragma unroll
      for(int f=0;f<4;f++){
        int cbase = n0/2 + f*8 + gid;
        b1[f][0]=__float_as_uint(ds[tig*LDD + cbase + 1]);
        b1[f][1]=__float_as_uint(ds[(tig+4)*LDD + cbase + 1]);
        b0[f][0]=__float_as_uint(ds[tig*LDD + cbase]);
        b0[f][1]=__float_as_uint(ds[(tig+4)*LDD + cbase]);
      }
#pragma unroll
      for(int kj=0;kj<3;kj++){
        const int tap=tapBase+kj;
#pragma unroll
        for(int mf=0;mf<2;mf++){
          unsigned a0=__float_as_uint(ws[(tap*8+tig)*LDW + m0+mf*16+gid]);
          unsigned a1=__float_as_uint(ws[(tap*8+tig)*LDW + m0+mf*16+gid+8]);
          unsigned a2=__float_as_uint(ws[(tap*8+tig+4)*LDW + m0+mf*16+gid]);
          unsigned a3=__float_as_uint(ws[(tap*8+tig+4)*LDW + m0+mf*16+gid+8]);
#pragma unroll
          for(int f=0;f<4;f++){
            float* c4 = (kj==1)? acc_o[mf][f] : acc_e[mf][f];
            const unsigned* bb = (kj==2)? b0[f] : b1[f];
            mma_tf32(c4, a0,a1,a2,a3, bb[0],bb[1]);
          }
        }
      }
    };
    proc(dsA, xe?0:3);
    if(hasB) proc(dsB, 6);
  }

#pragma unroll
  for(int mf=0;mf<2;mf++){
    int c0_=m0+mf*16+gid;
#pragma unroll
    for(int f=0;f<4;f++){
      int Y = y0 + n0 + 2*(f*8 + 2*tig);
      long b0i=(((long)n*CIN+c0_)*HIN+x)*WIN + Y;
      long b1i=(((long)n*CIN+c0_+8)*HIN+x)*WIN + Y;
      float2 m, r;
      m=*(const float2*)&act[b0i];
      r.x = m.x>0.f? acc_e[mf][f][0]:0.f; r.y = m.y>0.f? acc_o[mf][f][0]:0.f;
      *(float2*)&din[b0i]=r;
      m=*(const float2*)&act[b0i+2];
      r.x = m.x>0.f? acc_e[mf][f][1]:0.f; r.y = m.y>0.f? acc_o[mf][f][1]:0.f;
      *(float2*)&din[b0i+2]=r;
      m=*(const float2*)&act[b1i];
      r.x = m.x>0.f? acc_e[mf][f][2]:0.f; r.y = m.y>0.f? acc_o[mf][f][2]:0.f;
      *(float2*)&din[b1i]=r;
      m=*(const float2*)&act[b1i+2];
      r.x = m.x>0.f? acc_e[mf][f][3]:0.f; r.y = m.y>0.f? acc_o[mf][f][3]:0.f;
      *(float2*)&din[b1i+2]=r;
    }
  }
}

// ---------- conv1 data-grad -> |dx|, x-row-pair ----------
__global__ void __launch_bounds__(256) k_bwd1(
    const float* __restrict__ dz1, const float* __restrict__ W1,
    float* __restrict__ fam)
{
  __shared__ float ws[576];
  __shared__ float dsm[8*2*260];
  const int n=blockIdx.z, q=blockIdx.y, y0=blockIdx.x*512;
  const int tid=threadIdx.x;
  for(int idx=tid; idx<576; idx+=256) ws[idx]=W1[idx];
  const bool hasB=(q>0);
  const int jbase=y0/2-1;
  float aEE=0.f,aEO=0.f,aOE=0.f,aOO=0.f;
  for(int o0=0;o0<64;o0+=8){
    __syncthreads();
    for(int idx=tid; idx<8*2*260; idx+=256){
      int o=idx/520, rs=(idx/260)&1, jj=idx%260;
      int j=jbase+jj; int ir=rs? q-1 : q;
      float v=0.f;
      if(j>=0 && j<512 && (rs==0||hasB))
        v=dz1[(((long)n*64+o0+o)*64+ir)*512+j];
      dsm[idx]=v;
    }
    __syncthreads();
#pragma unroll
    for(int o=0;o<8;o++){
      const float* wb=&ws[(o0+o)*9];
      float vmA=dsm[(o*2)*260+tid], v0A=dsm[(o*2)*260+tid+1];
      aEE+=wb[0]*v0A+wb[2]*vmA; aEO+=wb[1]*v0A;
      if(hasB){
        float vmB=dsm[(o*2+1)*260+tid], v0B=dsm[(o*2+1)*260+tid+1];
        aEE+=wb[6]*v0B+wb[8]*vmB; aEO+=wb[7]*v0B;
      }
      aOE+=wb[3]*v0A+wb[5]*vmA; aOO+=wb[4]*v0A;
    }
  }
  long base=((long)n*128+2*q)*1024 + y0 + 2*tid;
  fam[base]=fabsf(aEE);      fam[base+1]=fabsf(aEO);
  fam[base+1024]=fabsf(aOE); fam[base+1025]=fabsf(aOO);
}

// ---------- att partial GEMM (S1, staging-side cvt) ----------
__global__ void __launch_bounds__(256) k_attp(
    const float* __restrict__ Wa, const float* __restrict__ feat,
    float* __restrict__ attp)
{
  constexpr int LDA=129, LDB=132;
  __shared__ float As[32*LDA];
  __shared__ float Bs[32*LDB];
  const int ks=blockIdx.x, b=blockIdx.y;
  const int tid=threadIdx.x, wid=tid>>5, lane=tid&31;
  const int gid=lane>>2, tig=lane&3;
  const int m0=(wid&3)*32, n0=(wid>>2)*64;
  const float* fb = feat + (long)b*524288;
  float acc[2][8][4];
#pragma unroll
  for(int a=0;a<2;a++)
#pragma unroll
  for(int bq=0;bq<8;bq++)
#pragma unroll
  for(int c=0;c<4;c++) acc[a][bq][c]=0.f;

  for(int k0=ks*512; k0<ks*512+512; k0+=32){
    __syncthreads();
    for(int idx=tid; idx<4096; idx+=256){
      int h=idx>>5, kk=idx&31;
      As[kk*LDA+h]=to_tf32(Wa[(long)h*4096+k0+kk]);
    }
    for(int idx=tid; idx<4096; idx+=256){
      int kk=idx>>7, t=idx&127;
      Bs[kk*LDB+t]=to_tf32(fb[(long)(k0+kk)*128+t]);
    }
    __syncthreads();
#pragma unroll
    for(int kc=0;kc<4;kc++){
      const int kb=kc*8;
      unsigned bh[8][2];
#pragma unroll
      for(int f=0;f<8;f++){
        bh[f][0]=__float_as_uint(Bs[(kb+tig)*LDB + n0+f*8+gid]);
        bh[f][1]=__float_as_uint(Bs[(kb+tig+4)*LDB + n0+f*8+gid]);
      }
#pragma unroll
      for(int mf=0;mf<2;mf++){
        unsigned a0=__float_as_uint(As[(kb+tig)*LDA + m0+mf*16+gid]);
        unsigned a1=__float_as_uint(As[(kb+tig)*LDA + m0+mf*16+gid+8]);
        unsigned a2=__float_as_uint(As[(kb+tig+4)*LDA + m0+mf*16+gid]);
        unsigned a3=__float_as_uint(As[(kb+tig+4)*LDA + m0+mf*16+gid+8]);
#pragma unroll
        for(int f=0;f<8;f++)
          mma_tf32(acc[mf][f], a0,a1,a2,a3, bh[f][0],bh[f][1]);
      }
    }
  }
#pragma unroll
  for(int mf=0;mf<2;mf++){
    int hA=m0+mf*16+gid, hB=hA+8;
#pragma unroll
    for(int f=0;f<8;f++){
      int t=n0+f*8+tig*2;
      float2 rA, rB;
      rA.x=acc[mf][f][0]; rA.y=acc[mf][f][1];
      rB.x=acc[mf][f][2]; rB.y=acc[mf][f][3];
      *(float2*)&attp[(long)ks*524288 + ((long)b*128+hA)*128+t]=rA;
      *(float2*)&attp[(long)ks*524288 + ((long)b*128+hB)*128+t]=rB;
    }
  }
}
__global__ void k_attf(const float* __restrict__ attp, const float* __restrict__ ba,
                       float* __restrict__ att)
{
  int i=blockIdx.x*256+threadIdx.x; if(i>=524288) return;
  int h=(i>>7)&127;
  float s=0.f;
#pragma unroll
  for(int ks=0;ks<8;ks++) s+=attp[(long)ks*524288+i];
  att[i]=tanhf(s+ba[h]);
}

// ---------- softmax ----------
__global__ void __launch_bounds__(128) k_salpha(
    const float* __restrict__ att, const float* __restrict__ va,
    float* __restrict__ alpha)
{
  __shared__ float vs[128], buf[128];
  const int b=blockIdx.x, t=threadIdx.x;
  vs[t]=va[t];
  __syncthreads();
  float s=0.f;
#pragma unroll 4
  for(int h=0;h<128;h++) s+=vs[h]*att[((long)b*128+h)*128+t];
  buf[t]=s; __syncthreads();
  for(int off=64;off;off>>=1){ if(t<off) buf[t]=fmaxf(buf[t],buf[t+off]); __syncthreads(); }
  float mx=buf[0]; __syncthreads();
  float e=expf(s-mx);
  buf[t]=e; __syncthreads();
  for(int off=64;off;off>>=1){ if(t<off) buf[t]+=buf[t+off]; __syncthreads(); }
  alpha[b*128+t]=e/buf[0];
}

// ---------- mu, m2 ----------
__global__ void k_mustats(const float* __restrict__ feat,
    const float* __restrict__ alpha, float* __restrict__ mu, float* __restrict__ m2)
{
  int w=(blockIdx.x*blockDim.x+threadIdx.x)>>5, lane=threadIdx.x&31;
  if(w>=131072) return;
  int b=w>>12;
  const float* fr=feat+(long)w*128;
  const float* ar=alpha+b*128;
  float s1=0.f,s2=0.f;
#pragma unroll
  for(int t=lane;t<128;t+=32){
    float a=ar[t], f=fr[t];
    s1+=a*f; s2+=a*f*f;
  }
  for(int o=16;o;o>>=1){ s1+=__shfl_down_sync(~0u,s1,o); s2+=__shfl_down_sync(~0u,s2,o); }
  if(!lane){ mu[w]=s1; m2[w]=s2; }
}

// ---------- gvec ----------
__global__ void k_gvec(const float* __restrict__ We,const float* __restrict__ Wc,
                       float* __restrict__ gvec)
{
  int w=(blockIdx.x*blockDim.x+threadIdx.x)>>5, lane=threadIdx.x&31;
  if(w>=8192) return;
  float s=0.f;
  for(int j=lane;j<256;j+=32) s+=We[(long)w*256+j]*(Wc[j*2+1]-Wc[j*2]);
  for(int o=16;o;o>>=1) s+=__shfl_down_sync(~0u,s,o);
  if(!lane) gvec[w]=s;
}

// ---------- dMu,dE2 ----------
__global__ void k_dcoef(const float* __restrict__ mu,const float* __restrict__ m2,
    const float* __restrict__ gvec, float* __restrict__ dMu,float* __restrict__ dE2)
{
  int i=blockIdx.x*256+threadIdx.x; if(i>=131072) return;
  int d=i&4095;
  float m=mu[i], v=m2[i]-m*m;
  float g2=gvec[4096+d];
  float dE=0.f, dM=gvec[d];
  if(v>1e-5f){ float sg=sqrtf(v); dE=0.5f*g2/sg; dM-=g2*m/sg; }
  dMu[i]=dM; dE2[i]=dE;
}

// ---------- dalpha ----------
__global__ void __launch_bounds__(128) k_dalp(
    const float* __restrict__ feat,const float* __restrict__ dMu,
    const float* __restrict__ dE2,float* __restrict__ part)
{
  const int ks=blockIdx.x, b=blockIdx.y, t=threadIdx.x;
  const float* fb=feat+(long)b*524288;
  const float* dm=dMu+b*4096; const float* de=dE2+b*4096;
  float acc=0.f;
  int d0=ks*512;
#pragma unroll 4
  for(int d=d0;d<d0+512;d++){
    float f=fb[(long)d*128+t];
    acc+=dm[d]*f+de[d]*f*f;
  }
  part[(ks*32+b)*128+t]=acc;
}
__global__ void __launch_bounds__(128) k_dalf(
    const float* __restrict__ part,const float* __restrict__ alpha,
    float* __restrict__ ds)
{
  const int b=blockIdx.x, t=threadIdx.x;
  float acc=0.f;
#pragma unroll
  for(int ks=0;ks<8;ks++) acc+=part[(ks*32+b)*128+t];
  __shared__ float buf[128];
  float a=alpha[b*128+t];
  buf[t]=a*acc; __syncthreads();
  for(int off=64;off;off>>=1){ if(t<off) buf[t]+=buf[t+off]; __syncthreads(); }
  ds[b*128+t]=a*(acc-buf[0]);
}

// ---------- dfeat (S1, dz computed in-staging) + fused epilogue ----------
__global__ void __launch_bounds__(256) k_dfeat(
    const float* __restrict__ Wa, const float* __restrict__ att,
    const float* __restrict__ va, const float* __restrict__ ds,
    const float* __restrict__ feat, const float* __restrict__ alpha,
    const float* __restrict__ dMu, const float* __restrict__ dE2,
    float* __restrict__ dout3)
{
  constexpr int LDA=132, LDB=132;
  __shared__ float As[32*LDA];
  __shared__ float Bs[32*LDB];
  __shared__ float al[128], vs[128], dsv[128];
  const int d0=blockIdx.x*128, b=blockIdx.y;
  const int tid=threadIdx.x, wid=tid>>5, lane=tid&31;
  const int gid=lane>>2, tig=lane&3;
  const int m0=(wid&3)*32, n0=(wid>>2)*64;
  if(tid<128){
    al[tid]=alpha[b*128+tid];
    vs[tid]=va[tid];
    dsv[tid]=ds[b*128+tid];
  }
  float acc[2][8][4];
#pragma unroll
  for(int a=0;a<2;a++)
#pragma unroll
  for(int bq=0;bq<8;bq++)
#pragma unroll
  for(int c=0;c<4;c++) acc[a][bq][c]=0.f;

  for(int k0=0;k0<128;k0+=32){
    __syncthreads();
    for(int idx=tid; idx<4096; idx+=256){
      int kk=idx>>7, dd=idx&127;
      As[kk*LDA+dd]=to_tf32(Wa[(long)(k0+kk)*4096+d0+dd]);
    }
    for(int idx=tid; idx<4096; idx+=256){
      int kk=idx>>7, t=idx&127;
      int h=k0+kk;
      float a=att[((long)b*128+h)*128+t];
      float dzv=vs[h]*dsv[t]*(1.f-a*a);
      Bs[kk*LDB+t]=to_tf32(dzv);
    }
    __syncthreads();
#pragma unroll
    for(int kc=0;kc<4;kc++){
      const int kb=kc*8;
      unsigned bh[8][2];
#pragma unroll
      for(int f=0;f<8;f++){
        bh[f][0]=__float_as_uint(Bs[(kb+tig)*LDB + n0+f*8+gid]);
        bh[f][1]=__float_as_uint(Bs[(kb+tig+4)*LDB + n0+f*8+gid]);
      }
#pragma unroll
      for(int mf=0;mf<2;mf++){
        unsigned a0=__float_as_uint(As[(kb+tig)*LDA + m0+mf*16+gid]);
        unsigned a1=__float_as_uint(As[(kb+tig)*LDA + m0+mf*16+gid+8]);
        unsigned a2=__float_as_uint(As[(kb+tig+4)*LDA + m0+mf*16+gid]);
        unsigned a3=__float_as_uint(As[(kb+tig+4)*LDA + m0+mf*16+gid+8]);
#pragma unroll
        for(int f=0;f<8;f++)
          mma_tf32(acc[mf][f], a0,a1,a2,a3, bh[f][0],bh[f][1]);
      }
    }
  }
#pragma unroll
  for(int mf=0;mf<2;mf++){
    int dA=d0+m0+mf*16+gid, dB=dA+8;
    float dmA=dMu[(long)b*4096+dA], deA=dE2[(long)b*4096+dA];
    float dmB=dMu[(long)b*4096+dB], deB=dE2[(long)b*4096+dB];
#pragma unroll
    for(int f=0;f<8;f++){
      int t=n0+f*8+tig*2;
      long fiA=((long)b*4096+dA)*128+t;
      long fiB=((long)b*4096+dB)*128+t;
      float2 fvA=*(const float2*)&feat[fiA];
      float2 fvB=*(const float2*)&feat[fiB];
      float2 rA, rB;
      rA.x = fvA.x>0.f? (acc[mf][f][0]+al[t]*(dmA+2.f*deA*fvA.x)) : 0.f;
      rA.y = fvA.y>0.f? (acc[mf][f][1]+al[t+1]*(dmA+2.f*deA*fvA.y)) : 0.f;
      rB.x = fvB.x>0.f? (acc[mf][f][2]+al[t]*(dmB+2.f*deB*fvB.x)) : 0.f;
      rB.y = fvB.y>0.f? (acc[mf][f][3]+al[t+1]*(dmB+2.f*deB*fvB.y)) : 0.f;
      *(float2*)&dout3[fiA]=rA;
      *(float2*)&dout3[fiB]=rB;
    }
  }
}

// ---------- row/col stats ----------
__global__ void k_rowstats(const float* __restrict__ fam,const float* __restrict__ x,
    float* __restrict__ cm,float* __restrict__ meanT)
{
  int w=(blockIdx.x*blockDim.x+threadIdx.x)>>5, lane=threadIdx.x&31;
  if(w>=4096) return;
  const float* fr=fam+(long)w*1024; const float* xr=x+(long)w*1024;
  float m=-1e30f, s=0.f;
  for(int t=lane;t<1024;t+=32){ m=fmaxf(m,fr[t]); s+=xr[t]; }
  for(int o=16;o;o>>=1){ m=fmaxf(m,__shfl_down_sync(~0u,m,o)); s+=__shfl_down_sync(~0u,s,o); }
  if(!lane){ cm[w]=m; meanT[w]=s*(1.f/1024.f); }
}
__global__ void k_colstats(const float* __restrict__ fam,const float* __restrict__ x,
    float* __restrict__ tm,float* __restrict__ meanF)
{
  int i=blockIdx.x*256+threadIdx.x; if(i>=32768) return;
  int b=i>>10, t=i&1023;
  const float* fb=fam+(long)b*131072+t; const float* xb=x+(long)b*131072+t;
  float m=-1e30f, s=0.f;
#pragma unroll 4
  for(int f=0;f<128;f++){ m=fmaxf(m,fb[f*1024]); s+=xb[f*1024]; }
  tm[i]=m; meanF[i]=s*(1.f/128.f);
}

// ---------- bitonic argsort ----------
template<int N>
__global__ void k_sort(const float* __restrict__ vals, int* __restrict__ idxout)
{
  __shared__ unsigned long long key[N];
  const int b=blockIdx.x, tid=threadIdx.x, TH=N/2;
  for(int i=tid;i<N;i+=TH){
    unsigned u=__float_as_uint(vals[b*N+i]);
    u = (u&0x80000000u)? ~u : (u|0x80000000u);
    key[i]=((unsigned long long)(~u)<<32)|(unsigned)i;
  }
  __syncthreads();
  for(int k=2;k<=N;k<<=1)
    for(int j=k>>1;j;j>>=1){
      for(int i=tid;i<N;i+=TH){
        int ixj=i^j;
        if(ixj>i){
          bool up=((i&k)==0);
          unsigned long long a=key[i],c=key[ixj];
          if((a>c)==up){ key[i]=c; key[ixj]=a; }
        }
      }
      __syncthreads();
    }
  for(int i=tid;i<128;i+=TH) idxout[b*128+i]=(int)(key[i]&0xFFFFFFFFu);
}

// ---------- RFM scan (parallel init) + mask prefixes ----------
__global__ void k_rfm(const int* __restrict__ sc,const int* __restrict__ st,
    const int* __restrict__ mask_t,const int* __restrict__ s_t,
    const int* __restrict__ is_train,int* __restrict__ rstep,int* __restrict__ cstep,
    int* __restrict__ rowp,int* __restrict__ colp)
{
  const int b=blockIdx.x, t=threadIdx.x;
  int* rs=rstep+b*128; int* cs=cstep+b*1024;
  rs[t]=-1;
  for(int i=t;i<1024;i+=128) cs[i]=-1;
  __syncthreads();
  if(t==0){
    bool train = !(is_train && is_train[0]==0);
    if(train){
      int cnt=0;
      for(int s=0;s<128 && cnt<3;s++){
        int pc=sc[b*128+s], pt=st[b*128+s];
        if(rs[pc]!=-1||cs[pt]!=-1) continue;
        int mt=mask_t[b*128+s], ss=s_t[b*128+s];
        rs[pc]=s;
        int l=pt-ss; if(l<0)l=0;
        int r=pt+mt-ss; if(r>1024)r=1024;
        for(int tt=l;tt<r;tt++) cs[tt]=s;
        cnt++;
      }
    }
    int acc=0;
    rowp[b*129]=0;
    for(int i=0;i<128;i++){ acc += (rs[i]>=0); rowp[b*129+i+1]=acc; }
    acc=0;
    colp[b*1025]=0;
    for(int i=0;i<1024;i++){ acc += (cs[i]>=0); colp[b*1025+i+1]=acc; }
  }
}

// ---------- apply mask ----------
__global__ void k_apply(const float* __restrict__ x,const int* __restrict__ rstep,
    const int* __restrict__ cstep,const float* __restrict__ meanT,
    const float* __restrict__ meanF,float* __restrict__ xm)
{
  long i=(long)blockIdx.x*256+threadIdx.x; if(i>=4194304) return;
  int t=(int)(i&1023); int f=(int)((i>>10)&127); int b=(int)(i>>17);
  int rs=rstep[b*128+f], cs=cstep[b*1024+t];
  float v;
  if(rs<0&&cs<0) v=x[i];
  else v=(cs>=rs)? meanT[b*128+f] : meanF[b*1024+t];
  xm[i]=v;
}

// ---------- emb head ----------
__global__ void k_cat(const float* __restrict__ mu,const float* __restrict__ m2,
                      float* __restrict__ cat)
{
  int i=blockIdx.x*256+threadIdx.x; if(i>=131072) return;
  int b=i>>12, d=i&4095;
  float m=mu[i];
  cat[(long)b*8192+d]=m;
  cat[(long)b*8192+4096+d]=sqrtf(fmaxf(m2[i]-m*m,1e-5f));
}
__global__ void __launch_bounds__(256) k_embp(
    const float* __restrict__ cat,const float* __restrict__ We,
    float* __restrict__ part)
{
  __shared__ float cs[32][64];
  const int ks=blockIdx.x, j=threadIdx.x;
  for(int idx=j; idx<32*64; idx+=256){
    int b=idx>>6, ii=idx&63;
    cs[b][ii]=cat[(long)b*8192 + ks*64 + ii];
  }
  __syncthreads();
  float acc[32];
#pragma unroll
  for(int b=0;b<32;b++) acc[b]=0.f;
  for(int ii=0;ii<64;ii++){
    float w=We[((long)ks*64+ii)*256+j];
#pragma unroll
    for(int b=0;b<32;b++) acc[b]+=cs[b][ii]*w;
  }
#pragma unroll
  for(int b=0;b<32;b++) part[((long)ks*32+b)*256+j]=acc[b];
}
__global__ void __launch_bounds__(256) k_embf(
    const float* __restrict__ part,const float* __restrict__ be,
    const float* __restrict__ Wc,const float* __restrict__ bc,
    float* __restrict__ out)
{
  const int b=blockIdx.x, j=threadIdx.x;
  float s=be[j];
  for(int ks=0;ks<128;ks++) s+=part[((long)ks*32+b)*256+j];
  __shared__ float es[256];
  es[j]=s; __syncthreads();
  if(j<2){
    float acc=bc[j];
    for(int q=0;q<256;q++) acc+=es[q]*Wc[q*2+j];
    out[b*2+j]=acc;
  }
}

// ---------- host ----------
static void run_tail(const float* h3,const float* Wa,const float* ba,const float* va,
                     float* attp,float* att,float* alpha,float* mu,float* m2)
{
  k_attp<<<dim3(8,32),256>>>(Wa,h3,attp);
  k_attf<<<2048,256>>>(attp,ba,att);
  k_salpha<<<32,128>>>(att,va,alpha);
  k_mustats<<<16384,256>>>(h3,alpha,mu,m2);
}

extern "C" void kernel_launch(void* const* d_in,const int* in_sizes,int n_in,
                              void* d_out,int out_size)
{
  const float* x =(const float*)d_in[0];
  const float* W1=(const float*)d_in[1]; const float* b1=(const float*)d_in[2];
  const float* W2=(const float*)d_in[3]; const float* b2=(const float*)d_in[4];
  const float* W3=(const float*)d_in[5]; const float* b3=(const float*)d_in[6];
  const float* Wa=(const float*)d_in[7]; const float* ba=(const float*)d_in[8];
  const float* va=(const float*)d_in[9];
  const float* We=(const float*)d_in[10]; const float* be=(const float*)d_in[11];
  const float* Wc=(const float*)d_in[12]; const float* bc=(const float*)d_in[13];
  const int* mask_t=(const int*)d_in[14]; const int* s_t=(const int*)d_in[15];
  const int* is_train = (n_in>16)? (const int*)d_in[16] : nullptr;
  float* out=(float*)d_out;

  float *h1,*h2,*h3,*d1,*d2,*d3,*fam,*xm,*att,*attp,*alpha,*ds,*dap,*mu,*m2,*dMu,*dE2,*gvec;
  float *cat,*ep,*cm,*tm,*meanT,*meanF,*wtf2,*wtb2,*wtf3,*wtb3;
  int *sc,*st,*rstep,*cstep,*rowp,*colp;
  cudaGetSymbolAddress((void**)&h1,g_h1);   cudaGetSymbolAddress((void**)&h2,g_h2);
  cudaGetSymbolAddress((void**)&h3,g_h3);   cudaGetSymbolAddress((void**)&d1,g_d1);
  cudaGetSymbolAddress((void**)&d2,g_d2);   cudaGetSymbolAddress((void**)&d3,g_d3);
  cudaGetSymbolAddress((void**)&fam,g_fam); cudaGetSymbolAddress((void**)&xm,g_xm);
  cudaGetSymbolAddress((void**)&att,g_att); cudaGetSymbolAddress((void**)&attp,g_attp);
  cudaGetSymbolAddress((void**)&alpha,g_alpha); cudaGetSymbolAddress((void**)&ds,g_dsb);
  cudaGetSymbolAddress((void**)&dap,g_dap);
  cudaGetSymbolAddress((void**)&mu,g_mu);   cudaGetSymbolAddress((void**)&m2,g_m2);
  cudaGetSymbolAddress((void**)&dMu,g_dMu); cudaGetSymbolAddress((void**)&dE2,g_dE2);
  cudaGetSymbolAddress((void**)&gvec,g_gvec);
  cudaGetSymbolAddress((void**)&cat,g_cat); cudaGetSymbolAddress((void**)&ep,g_ep);
  cudaGetSymbolAddress((void**)&cm,g_cm);   cudaGetSymbolAddress((void**)&tm,g_tm);
  cudaGetSymbolAddress((void**)&meanT,g_meanT); cudaGetSymbolAddress((void**)&meanF,g_meanF);
  cudaGetSymbolAddress((void**)&sc,g_sc);   cudaGetSymbolAddress((void**)&st,g_st);
  cudaGetSymbolAddress((void**)&rstep,g_rstep); cudaGetSymbolAddress((void**)&cstep,g_cstep);
  cudaGetSymbolAddress((void**)&rowp,g_rowp);   cudaGetSymbolAddress((void**)&colp,g_colp);
  cudaGetSymbolAddress((void**)&wtf2,g_wtf2); cudaGetSymbolAddress((void**)&wtb2,g_wtb2);
  cudaGetSymbolAddress((void**)&wtf3,g_wtf3); cudaGetSymbolAddress((void**)&wtb3,g_wtb3);

  const int SMEM1 = 120*136*4;
  const int SMEM3 = 168*136*4;
  cudaFuncSetAttribute(k_cmma<64,128,64,512,1>,  cudaFuncAttributeMaxDynamicSharedMemorySize, SMEM1);
  cudaFuncSetAttribute(k_cmma<64,128,64,512,3>,  cudaFuncAttributeMaxDynamicSharedMemorySize, SMEM3);
  cudaFuncSetAttribute(k_cmma<128,256,32,256,1>, cudaFuncAttributeMaxDynamicSharedMemorySize, SMEM1);
  cudaFuncSetAttribute(k_cmma<128,256,32,256,3>, cudaFuncAttributeMaxDynamicSharedMemorySize, SMEM3);

  // prep
  k_wt<<<288,256>>>(W2,wtf2,wtb2,64,128);
  k_wt<<<1152,256>>>(W3,wtf3,wtb3,128,256);
  k_gvec<<<1024,256>>>(We,Wc,gvec);
  // pass 1: forward convs 3xTF32 (argsort-critical)
  k_conv1<<<dim3(8,64,32),256>>>(x,W1,b1,h1,nullptr,nullptr);
  k_cmma<64,128,64,512,3><<<dim3(2,32,32),256,SMEM3>>>(h1,wtf2,b2,h2);
  k_cmma<128,256,32,256,3><<<dim3(2,16,32),256,SMEM3>>>(h2,wtf3,b3,h3);
  run_tail(h3,Wa,ba,va,attp,att,alpha,mu,m2);
  // backward to input: single-tf32
  k_dcoef<<<512,256>>>(mu,m2,gvec,dMu,dE2);
  k_dalp<<<dim3(8,32),128>>>(h3,dMu,dE2,dap);
  k_dalf<<<32,128>>>(dap,alpha,ds);
  k_dfeat<<<dim3(32,32),256>>>(Wa,att,va,ds,h3,alpha,dMu,dE2,d3);
  k_cbmma<128,256,16,128,128><<<dim3(2,32,32),256>>>(d3,wtb3,h2,d2);
  k_cbmma<64,128,32,256,256><<<dim3(2,64,32),256>>>(d2,wtb2,h1,d1);
  k_bwd1<<<dim3(2,64,32),256>>>(d1,W1,fam);
  // masking
  k_rowstats<<<512,256>>>(fam,x,cm,meanT);
  k_colstats<<<128,256>>>(fam,x,tm,meanF);
  k_sort<128><<<32,64>>>(cm,sc);
  k_sort<1024><<<32,512>>>(tm,st);
  k_rfm<<<32,128>>>(sc,st,mask_t,s_t,is_train,rstep,cstep,rowp,colp);
  k_apply<<<16384,256>>>(x,rstep,cstep,meanT,meanF,xm);
  // pass 2 (single tf32); conv1 updates h1 in place, skipping unmasked tiles
  k_conv1<<<dim3(8,64,32),256>>>(xm,W1,b1,h1,rowp,colp);
  k_cmma<64,128,64,512,1><<<dim3(2,32,32),256,SMEM1>>>(h1,wtf2,b2,h2);
  k_cmma<128,256,32,256,1><<<dim3(2,16,32),256,SMEM1>>>(h2,wtf3,b3,h3);
  run_tail(h3,Wa,ba,va,attp,att,alpha,mu,m2);
  k_cat<<<512,256>>>(mu,m2,cat);
  k_embp<<<128,256>>>(cat,We,ep);
  k_embf<<<32,256>>>(ep,be,Wc,bc,out);
}

// round 16
// speedup vs baseline: 1.0180x; 1.0063x over previous
#include <cuda_runtime.h>
#include <math.h>

// ---------- static scratch ----------
__device__ float g_h1[67108864];
__device__ float g_h2[33554432];
__device__ float g_h3[16777216];
__device__ float g_d1[67108864];
__device__ float g_d2[33554432];
__device__ float g_d3[16777216];
__device__ float g_fam[4194304];
__device__ float g_xm[4194304];
__device__ float g_att[524288];
__device__ float g_attp[4194304];
__device__ float g_alpha[4096];
__device__ float g_dsb[4096];
__device__ float g_dap[32768];
__device__ float g_mu[131072];
__device__ float g_m2[131072];
__device__ float g_dMu[131072];
__device__ float g_dE2[131072];
__device__ float g_gvec[8192];
__device__ float g_cat[262144];
__device__ float g_ep[1048576];
__device__ float g_cm[4096];
__device__ float g_tm[32768];
__device__ float g_meanT[4096];
__device__ float g_meanF[32768];
__device__ int   g_sc[4096];
__device__ int   g_st[4096];
__device__ int   g_rstep[4096];
__device__ int   g_cstep[32768];
__device__ int   g_rowp[4128];
__device__ int   g_colp[32800];
__device__ float g_wtf2[73728];
__device__ float g_wtb2[73728];
__device__ float g_wtf3[294912];
__device__ float g_wtb3[294912];

// ---------- weight transposes ----------
__global__ void k_wt(const float* __restrict__ W, float* __restrict__ WTf,
                     float* __restrict__ WTb, int CIN, int COUT)
{
  int idx=blockIdx.x*256+threadIdx.x;
  int tot=CIN*COUT*9; if(idx>=tot) return;
  int k=idx%9, c=(idx/9)%CIN, o=idx/(9*CIN);
  float v=W[idx];
  int rf=(c>>3)*72 + k*8 + (c&7);
  WTf[(long)rf*COUT+o]=v;
  int rb=(o>>3)*72 + k*8 + (o&7);
  WTb[(long)rb*CIN+c]=v;
}

// ---------- conv1 fwd (compile-time skip variant) ----------
template<int SKIP>
__global__ void __launch_bounds__(256) k_conv1(
    const float* __restrict__ in, const float* __restrict__ W,
    const float* __restrict__ bias, float* __restrict__ out,
    const int* __restrict__ rowp, const int* __restrict__ colp)
{
  __shared__ __align__(16) float ins[3][132];
  __shared__ __align__(16) float ws[9][64];
  __shared__ float bs[64];
  const int n=blockIdx.z, i=blockIdx.y, j0=blockIdx.x*64;
  if(SKIP){
    int r0=2*i, r1=2*i+3; if(r1>128) r1=128;
    int c0=2*j0, c1=2*j0+130; if(c1>1024) c1=1024;
    if(rowp[n*129+r1]==rowp[n*129+r0] && colp[n*1025+c1]==colp[n*1025+c0]) return;
  }
  const int tid=threadIdx.x, jt=tid&15, og=tid>>4;
  for(int idx=tid; idx<576; idx+=256){
    int o=idx/9, k=idx%9;
    ws[k][o]=W[idx];
  }
  if(tid<64) bs[tid]=bias[tid];
  for(int idx=tid; idx<3*130; idx+=256){
    int r=idx/130, col=idx%130;
    int gx=2*i+r, gy=2*j0+col;
    float v=0.f;
    if(gx<128 && gy<1024) v=in[((long)n*128+gx)*1024+gy];
    ins[r][col]=v;
  }
  __syncthreads();
  float acc[4][4];
#pragma unroll
  for(int o=0;o<4;o++)
#pragma unroll
  for(int e=0;e<4;e++) acc[o][e]=0.f;
#pragma unroll
  for(int r=0;r<3;r++){
    float v[9];
    *(float4*)v     = *(float4*)&ins[r][8*jt];
    *(float4*)(v+4) = *(float4*)&ins[r][8*jt+4];
    v[8]            = ins[r][8*jt+8];
#pragma unroll
    for(int kj=0;kj<3;kj++){
      float w[4];
      *(float4*)w = *(float4*)&ws[r*3+kj][og*4];
#pragma unroll
      for(int oo=0;oo<4;oo++)
#pragma unroll
      for(int e=0;e<4;e++)
        acc[oo][e]+=w[oo]*v[2*e+kj];
    }
  }
#pragma unroll
  for(int oo=0;oo<4;oo++){
    int o=og*4+oo;
    float bb=bs[o];
    float4 r;
    r.x=fmaxf(acc[oo][0]+bb,0.f); r.y=fmaxf(acc[oo][1]+bb,0.f);
    r.z=fmaxf(acc[oo][2]+bb,0.f); r.w=fmaxf(acc[oo][3]+bb,0.f);
    *(float4*)&out[(((long)n*64+o)*64+i)*512 + j0 + 4*jt]=r;
  }
}

// ---------- tf32 helpers ----------
__device__ __forceinline__ float to_tf32(float v){
  unsigned r; asm("cvt.rna.tf32.f32 %0, %1;" : "=r"(r) : "f"(v));
  return __uint_as_float(r);
}
__device__ __forceinline__ void mma_tf32(float* c4,
    unsigned a0,unsigned a1,unsigned a2,unsigned a3,unsigned b0,unsigned b1){
  asm volatile(
    "mma.sync.aligned.m16n8k8.row.col.f32.tf32.tf32.f32 "
    "{%0,%1,%2,%3},{%4,%5,%6,%7},{%8,%9},{%0,%1,%2,%3};"
    : "+f"(c4[0]),"+f"(c4[1]),"+f"(c4[2]),"+f"(c4[3])
    : "r"(a0),"r"(a1),"r"(a2),"r"(a3),"r"(b0),"r"(b1));
}

// ---------- tf32 mma conv fwd; staging-side cvt ----------
template<int CIN,int COUT,int HIN,int WIN,int SPLIT>
__global__ void __launch_bounds__(256,2) k_cmma(
    const float* __restrict__ in, const float* __restrict__ WT,
    const float* __restrict__ bias, float* __restrict__ out)
{
  constexpr int HOUT=HIN/2, WOUT=WIN/2;
  constexpr int NJT=WOUT/128;
  constexpr int LD=136;
  constexpr int WOFF=(SPLIT==3)?96:48;
  extern __shared__ float sm[];
  float* evh = sm;
  float* odh = sm + 24*LD;
  float* evl = sm + 48*LD;
  float* odl = sm + 72*LD;
  float* ws  = sm + WOFF*LD;
  const int n=blockIdx.z, i=blockIdx.y;
  const int jt_=blockIdx.x%NJT, ot=blockIdx.x/NJT;
  const int j0=jt_*128, o0=ot*128;
  const int tid=threadIdx.x, wid=tid>>5, lane=tid&31;
  const int gid=lane>>2, tig=lane&3;
  const int m0=(wid&3)*32, n0w=(wid>>2)*64;
  float acc[2][8][4];
#pragma unroll
  for(int a=0;a<2;a++)
#pragma unroll
  for(int b=0;b<8;b++)
#pragma unroll
  for(int c=0;c<4;c++) acc[a][b][c]=0.f;

  for(int c0=0;c0<CIN;c0+=8){
    __syncthreads();
    for(int idx=tid; idx<8*3*129; idx+=256){
      int c=idx/387, rem=idx%387, r=rem/129, p=rem%129;
      int gx=2*i+r, gy=2*j0+2*p;
      float a=0.f,bv=0.f;
      if(gx<HIN && gy<WIN){
        const float2 s=*(const float2*)&in[(((long)n*CIN+c0+c)*HIN+gx)*WIN+gy];
        a=s.x; bv=s.y;
      }
      float ah=to_tf32(a), bh=to_tf32(bv);
      evh[(c*3+r)*LD+p]=ah;
      odh[(c*3+r)*LD+p]=bh;
      if(SPLIT==3){
        evl[(c*3+r)*LD+p]=to_tf32(a-ah);
        odl[(c*3+r)*LD+p]=to_tf32(bv-bh);
      }
    }
    {
      const float* wsrc = WT + (long)(c0>>3)*72*COUT + o0;
      for(int idx=tid; idx<72*32; idx+=256){
        int kk=idx>>5, o4=(idx&31)*4;
        float4 v=*(const float4*)&wsrc[(long)kk*COUT + o4];
        if(SPLIT==1){ v.x=to_tf32(v.x); v.y=to_tf32(v.y); v.z=to_tf32(v.z); v.w=to_tf32(v.w); }
        *(float4*)&ws[kk*LD + o4]=v;
      }
    }
    __syncthreads();
#pragma unroll
    for(int kc=0;kc<9;kc++){
      const int r=kc/3, kj=kc%3;
      const float* srch = (kj==1)? odh : evh;
      const float* srcl = (kj==1)? odl : evl;
      const int co = (kj==2)? 1:0;
      unsigned bh[8][2], bl[8][2];
#pragma unroll
      for(int f=0;f<8;f++){
        int i0=(tig*3+r)*LD + n0w + f*8 + gid + co;
        int i1=((tig+4)*3+r)*LD + n0w + f*8 + gid + co;
        bh[f][0]=__float_as_uint(srch[i0]);
        bh[f][1]=__float_as_uint(srch[i1]);
        if(SPLIT==3){
          bl[f][0]=__float_as_uint(srcl[i0]);
          bl[f][1]=__float_as_uint(srcl[i1]);
        }
      }
#pragma unroll
      for(int mf=0;mf<2;mf++){
        unsigned ah0,ah1,ah2,ah3,al0=0,al1=0,al2=0,al3=0;
        if(SPLIT==1){
          ah0=__float_as_uint(ws[(kc*8+tig)*LD + m0+mf*16+gid]);
          ah1=__float_as_uint(ws[(kc*8+tig)*LD + m0+mf*16+gid+8]);
          ah2=__float_as_uint(ws[(kc*8+tig+4)*LD + m0+mf*16+gid]);
          ah3=__float_as_uint(ws[(kc*8+tig+4)*LD + m0+mf*16+gid+8]);
        }else{
          float w0=ws[(kc*8+tig)*LD + m0+mf*16+gid];
          float w1=ws[(kc*8+tig)*LD + m0+mf*16+gid+8];
          float w2=ws[(kc*8+tig+4)*LD + m0+mf*16+gid];
          float w3=ws[(kc*8+tig+4)*LD + m0+mf*16+gid+8];
          float h0=to_tf32(w0),h1=to_tf32(w1),h2=to_tf32(w2),h3=to_tf32(w3);
          ah0=__float_as_uint(h0); ah1=__float_as_uint(h1);
          ah2=__float_as_uint(h2); ah3=__float_as_uint(h3);
          al0=__float_as_uint(to_tf32(w0-h0)); al1=__float_as_uint(to_tf32(w1-h1));
          al2=__float_as_uint(to_tf32(w2-h2)); al3=__float_as_uint(to_tf32(w3-h3));
        }
#pragma unroll
        for(int f=0;f<8;f++){
          mma_tf32(acc[mf][f], ah0,ah1,ah2,ah3, bh[f][0],bh[f][1]);
          if(SPLIT==3){
            mma_tf32(acc[mf][f], ah0,ah1,ah2,ah3, bl[f][0],bl[f][1]);
            mma_tf32(acc[mf][f], al0,al1,al2,al3, bh[f][0],bh[f][1]);
          }
        }
      }
    }
  }
#pragma unroll
  for(int mf=0;mf<2;mf++){
    int oA=o0+m0+mf*16+gid, oB=oA+8;
    float bA=bias[oA], bB=bias[oB];
#pragma unroll
    for(int f=0;f<8;f++){
      int jj=j0 + n0w + f*8 + tig*2;
      long baseA=(((long)n*COUT+oA)*HOUT+i)*WOUT + jj;
      long baseB=(((long)n*COUT+oB)*HOUT+i)*WOUT + jj;
      float2 rA, rB;
      rA.x=fmaxf(acc[mf][f][0]+bA,0.f); rA.y=fmaxf(acc[mf][f][1]+bA,0.f);
      rB.x=fmaxf(acc[mf][f][2]+bB,0.f); rB.y=fmaxf(acc[mf][f][3]+bB,0.f);
      *(float2*)&out[baseA]=rA;
      *(float2*)&out[baseB]=rB;
    }
  }
}

// ---------- tf32 mma transposed-conv bwd (S1, staging-side cvt) ----------
template<int CIN,int COUT,int HOUT,int WOUT,int NT>
__global__ void __launch_bounds__(256,2) k_cbmma(
    const float* __restrict__ dout, const float* __restrict__ WT,
    const float* __restrict__ act, float* __restrict__ din)
{
  constexpr int HIN=2*HOUT, WIN=2*WOUT;
  constexpr int LDW=CIN+8, LDD=NT/2+4, JL=NT/2+2;
  constexpr int NW_M=CIN/32;
  __shared__ float ws[72*LDW];
  __shared__ float dsA[8*LDD];
  __shared__ float dsB[8*LDD];
  const int n=blockIdx.z, x=blockIdx.y, y0=blockIdx.x*NT;
  const int tid=threadIdx.x, wid=tid>>5, lane=tid&31;
  const int gid=lane>>2, tig=lane&3;
  const int m0=(wid%NW_M)*32, n0=(wid/NW_M)*64;
  const bool xe=((x&1)==0);
  const int iA = xe ? (x>>1) : ((x-1)>>1);
  const int iB = (x>>1)-1;
  const bool hasB = xe && iB>=0;
  const int jb = y0/2 - 1;
  float acc_e[2][4][4], acc_o[2][4][4];
#pragma unroll
  for(int a=0;a<2;a++)
#pragma unroll
  for(int b=0;b<4;b++)
#pragma unroll
  for(int c=0;c<4;c++){acc_e[a][b][c]=0.f; acc_o[a][b][c]=0.f;}

  for(int o0=0;o0<COUT;o0+=8){
    __syncthreads();
    {
      const float* wsrc = WT + (long)(o0>>3)*72*CIN;
      for(int idx=tid; idx<72*(CIN/4); idx+=256){
        int r=idx/(CIN/4), c4=(idx%(CIN/4))*4;
        float4 v=*(const float4*)&wsrc[(long)r*CIN+c4];
        v.x=to_tf32(v.x); v.y=to_tf32(v.y); v.z=to_tf32(v.z); v.w=to_tf32(v.w);
        *(float4*)&ws[r*LDW+c4]=v;
      }
    }
    for(int idx=tid; idx<8*JL; idx+=256){
      int o=idx/JL, jl=idx%JL; int j=jb+jl;
      float a=0.f,bv=0.f;
      if(j>=0 && j<WOUT){
        long base=((long)n*COUT+o0+o)*HOUT;
        a = dout[(base+iA)*WOUT+j];
        if(hasB) bv = dout[(base+iB)*WOUT+j];
      }
      dsA[o*LDD+jl]=to_tf32(a); dsB[o*LDD+jl]=to_tf32(bv);
    }
    __syncthreads();

    auto proc = [&](const float* ds, const int tapBase){
      unsigned b1[4][2], b0[4][2];
#pragma unroll
      for(int f=0;f<4;f++){
        int cbase = n0/2 + f*8 + gid;
        b1[f][0]=__float_as_uint(ds[tig*LDD + cbase + 1]);
        b1[f][1]=__float_as_uint(ds[(tig+4)*LDD + cbase + 1]);
        b0[f][0]=__float_as_uint(ds[tig*LDD + cbase]);
        b0[f][1]=__float_as_uint(ds[(tig+4)*LDD + cbase]);
      }
#pragma unroll
      for(int kj=0;kj<3;kj++){
        const int tap=tapBase+kj;
#pragma unroll
        for(int mf=0;mf<2;mf++){
          unsigned a0=__float_as_uint(ws[(tap*8+tig)*LDW + m0+mf*16+gid]);
          unsigned a1=__float_as_uint(ws[(tap*8+tig)*LDW + m0+mf*16+gid+8]);
          unsigned a2=__float_as_uint(ws[(tap*8+tig+4)*LDW + m0+mf*16+gid]);
          unsigned a3=__float_as_uint(ws[(tap*8+tig+4)*LDW + m0+mf*16+gid+8]);
#pragma unroll
          for(int f=0;f<4;f++){
            float* c4 = (kj==1)? acc_o[mf][f] : acc_e[mf][f];
            const unsigned* bb = (kj==2)? b0[f] : b1[f];
            mma_tf32(c4, a0,a1,a2,a3, bb[0],bb[1]);
          }
        }
      }
    };
    proc(dsA, xe?0:3);
    if(hasB) proc(dsB, 6);
  }

#pragma unroll
  for(int mf=0;mf<2;mf++){
    int c0_=m0+mf*16+gid;
#pragma unroll
    for(int f=0;f<4;f++){
      int Y = y0 + n0 + 2*(f*8 + 2*tig);
      long b0i=(((long)n*CIN+c0_)*HIN+x)*WIN + Y;
      long b1i=(((long)n*CIN+c0_+8)*HIN+x)*WIN + Y;
      float2 m, r;
      m=*(const float2*)&act[b0i];
      r.x = m.x>0.f? acc_e[mf][f][0]:0.f; r.y = m.y>0.f? acc_o[mf][f][0]:0.f;
      *(float2*)&din[b0i]=r;
      m=*(const float2*)&act[b0i+2];
      r.x = m.x>0.f? acc_e[mf][f][1]:0.f; r.y = m.y>0.f? acc_o[mf][f][1]:0.f;
      *(float2*)&din[b0i+2]=r;
      m=*(const float2*)&act[b1i];
      r.x = m.x>0.f? acc_e[mf][f][2]:0.f; r.y = m.y>0.f? acc_o[mf][f][2]:0.f;
      *(float2*)&din[b1i]=r;
      m=*(const float2*)&act[b1i+2];
      r.x = m.x>0.f? acc_e[mf][f][3]:0.f; r.y = m.y>0.f? acc_o[mf][f][3]:0.f;
      *(float2*)&din[b1i+2]=r;
    }
  }
}

// ---------- conv1 data-grad -> |dx|, x-row-pair ----------
__global__ void __launch_bounds__(256) k_bwd1(
    const float* __restrict__ dz1, const float* __restrict__ W1,
    float* __restrict__ fam)
{
  __shared__ float ws[576];
  __shared__ float dsm[8*2*260];
  const int n=blockIdx.z, q=blockIdx.y, y0=blockIdx.x*512;
  const int tid=threadIdx.x;
  for(int idx=tid; idx<576; idx+=256) ws[idx]=W1[idx];
  const bool hasB=(q>0);
  const int jbase=y0/2-1;
  float aEE=0.f,aEO=0.f,aOE=0.f,aOO=0.f;
  for(int o0=0;o0<64;o0+=8){
    __syncthreads();
    for(int idx=tid; idx<8*2*260; idx+=256){
      int o=idx/520, rs=(idx/260)&1, jj=idx%260;
      int j=jbase+jj; int ir=rs? q-1 : q;
      float v=0.f;
      if(j>=0 && j<512 && (rs==0||hasB))
        v=dz1[(((long)n*64+o0+o)*64+ir)*512+j];
      dsm[idx]=v;
    }
    __syncthreads();
#pragma unroll
    for(int o=0;o<8;o++){
      const float* wb=&ws[(o0+o)*9];
      float vmA=dsm[(o*2)*260+tid], v0A=dsm[(o*2)*260+tid+1];
      aEE+=wb[0]*v0A+wb[2]*vmA; aEO+=wb[1]*v0A;
      if(hasB){
        float vmB=dsm[(o*2+1)*260+tid], v0B=dsm[(o*2+1)*260+tid+1];
        aEE+=wb[6]*v0B+wb[8]*vmB; aEO+=wb[7]*v0B;
      }
      aOE+=wb[3]*v0A+wb[5]*vmA; aOO+=wb[4]*v0A;
    }
  }
  long base=((long)n*128+2*q)*1024 + y0 + 2*tid;
  fam[base]=fabsf(aEE);      fam[base+1]=fabsf(aEO);
  fam[base+1024]=fabsf(aOE); fam[base+1025]=fabsf(aOO);
}

// ---------- att partial GEMM (S1, staging-side cvt) ----------
__global__ void __launch_bounds__(256) k_attp(
    const float* __restrict__ Wa, const float* __restrict__ feat,
    float* __restrict__ attp)
{
  constexpr int LDA=129, LDB=132;
  __shared__ float As[32*LDA];
  __shared__ float Bs[32*LDB];
  const int ks=blockIdx.x, b=blockIdx.y;
  const int tid=threadIdx.x, wid=tid>>5, lane=tid&31;
  const int gid=lane>>2, tig=lane&3;
  const int m0=(wid&3)*32, n0=(wid>>2)*64;
  const float* fb = feat + (long)b*524288;
  float acc[2][8][4];
#pragma unroll
  for(int a=0;a<2;a++)
#pragma unroll
  for(int bq=0;bq<8;bq++)
#pragma unroll
  for(int c=0;c<4;c++) acc[a][bq][c]=0.f;

  for(int k0=ks*512; k0<ks*512+512; k0+=32){
    __syncthreads();
    for(int idx=tid; idx<4096; idx+=256){
      int h=idx>>5, kk=idx&31;
      As[kk*LDA+h]=to_tf32(Wa[(long)h*4096+k0+kk]);
    }
    for(int idx=tid; idx<4096; idx+=256){
      int kk=idx>>7, t=idx&127;
      Bs[kk*LDB+t]=to_tf32(fb[(long)(k0+kk)*128+t]);
    }
    __syncthreads();
#pragma unroll
    for(int kc=0;kc<4;kc++){
      const int kb=kc*8;
      unsigned bh[8][2];
#pragma unroll
      for(int f=0;f<8;f++){
        bh[f][0]=__float_as_uint(Bs[(kb+tig)*LDB + n0+f*8+gid]);
        bh[f][1]=__float_as_uint(Bs[(kb+tig+4)*LDB + n0+f*8+gid]);
      }
#pragma unroll
      for(int mf=0;mf<2;mf++){
        unsigned a0=__float_as_uint(As[(kb+tig)*LDA + m0+mf*16+gid]);
        unsigned a1=__float_as_uint(As[(kb+tig)*LDA + m0+mf*16+gid+8]);
        unsigned a2=__float_as_uint(As[(kb+tig+4)*LDA + m0+mf*16+gid]);
        unsigned a3=__float_as_uint(As[(kb+tig+4)*LDA + m0+mf*16+gid+8]);
#pragma unroll
        for(int f=0;f<8;f++)
          mma_tf32(acc[mf][f], a0,a1,a2,a3, bh[f][0],bh[f][1]);
      }
    }
  }
#pragma unroll
  for(int mf=0;mf<2;mf++){
    int hA=m0+mf*16+gid, hB=hA+8;
#pragma unroll
    for(int f=0;f<8;f++){
      int t=n0+f*8+tig*2;
      float2 rA, rB;
      rA.x=acc[mf][f][0]; rA.y=acc[mf][f][1];
      rB.x=acc[mf][f][2]; rB.y=acc[mf][f][3];
      *(float2*)&attp[(long)ks*524288 + ((long)b*128+hA)*128+t]=rA;
      *(float2*)&attp[(long)ks*524288 + ((long)b*128+hB)*128+t]=rB;
    }
  }
}
__global__ void k_attf(const float* __restrict__ attp, const float* __restrict__ ba,
                       float* __restrict__ att)
{
  int i=blockIdx.x*256+threadIdx.x; if(i>=524288) return;
  int h=(i>>7)&127;
  float s=0.f;
#pragma unroll
  for(int ks=0;ks<8;ks++) s+=attp[(long)ks*524288+i];
  att[i]=tanhf(s+ba[h]);
}

// ---------- softmax ----------
__global__ void __launch_bounds__(128) k_salpha(
    const float* __restrict__ att, const float* __restrict__ va,
    float* __restrict__ alpha)
{
  __shared__ float vs[128], buf[128];
  const int b=blockIdx.x, t=threadIdx.x;
  vs[t]=va[t];
  __syncthreads();
  float s=0.f;
#pragma unroll 4
  for(int h=0;h<128;h++) s+=vs[h]*att[((long)b*128+h)*128+t];
  buf[t]=s; __syncthreads();
  for(int off=64;off;off>>=1){ if(t<off) buf[t]=fmaxf(buf[t],buf[t+off]); __syncthreads(); }
  float mx=buf[0]; __syncthreads();
  float e=expf(s-mx);
  buf[t]=e; __syncthreads();
  for(int off=64;off;off>>=1){ if(t<off) buf[t]+=buf[t+off]; __syncthreads(); }
  alpha[b*128+t]=e/buf[0];
}

// ---------- mu, m2 ----------
__global__ void k_mustats(const float* __restrict__ feat,
    const float* __restrict__ alpha, float* __restrict__ mu, float* __restrict__ m2)
{
  int w=(blockIdx.x*blockDim.x+threadIdx.x)>>5, lane=threadIdx.x&31;
  if(w>=131072) return;
  int b=w>>12;
  const float* fr=feat+(long)w*128;
  const float* ar=alpha+b*128;
  float s1=0.f,s2=0.f;
#pragma unroll
  for(int t=lane;t<128;t+=32){
    float a=ar[t], f=fr[t];
    s1+=a*f; s2+=a*f*f;
  }
  for(int o=16;o;o>>=1){ s1+=__shfl_down_sync(~0u,s1,o); s2+=__shfl_down_sync(~0u,s2,o); }
  if(!lane){ mu[w]=s1; m2[w]=s2; }
}

// ---------- gvec ----------
__global__ void k_gvec(const float* __restrict__ We,const float* __restrict__ Wc,
                       float* __restrict__ gvec)
{
  int w=(blockIdx.x*blockDim.x+threadIdx.x)>>5, lane=threadIdx.x&31;
  if(w>=8192) return;
  float s=0.f;
  for(int j=lane;j<256;j+=32) s+=We[(long)w*256+j]*(Wc[j*2+1]-Wc[j*2]);
  for(int o=16;o;o>>=1) s+=__shfl_down_sync(~0u,s,o);
  if(!lane) gvec[w]=s;
}

// ---------- dMu,dE2 ----------
__global__ void k_dcoef(const float* __restrict__ mu,const float* __restrict__ m2,
    const float* __restrict__ gvec, float* __restrict__ dMu,float* __restrict__ dE2)
{
  int i=blockIdx.x*256+threadIdx.x; if(i>=131072) return;
  int d=i&4095;
  float m=mu[i], v=m2[i]-m*m;
  float g2=gvec[4096+d];
  float dE=0.f, dM=gvec[d];
  if(v>1e-5f){ float sg=sqrtf(v); dE=0.5f*g2/sg; dM-=g2*m/sg; }
  dMu[i]=dM; dE2[i]=dE;
}

// ---------- dalpha ----------
__global__ void __launch_bounds__(128) k_dalp(
    const float* __restrict__ feat,const float* __restrict__ dMu,
    const float* __restrict__ dE2,float* __restrict__ part)
{
  const int ks=blockIdx.x, b=blockIdx.y, t=threadIdx.x;
  const float* fb=feat+(long)b*524288;
  const float* dm=dMu+b*4096; const float* de=dE2+b*4096;
  float acc=0.f;
  int d0=ks*512;
#pragma unroll 4
  for(int d=d0;d<d0+512;d++){
    float f=fb[(long)d*128+t];
    acc+=dm[d]*f+de[d]*f*f;
  }
  part[(ks*32+b)*128+t]=acc;
}
__global__ void __launch_bounds__(128) k_dalf(
    const float* __restrict__ part,const float* __restrict__ alpha,
    float* __restrict__ ds)
{
  const int b=blockIdx.x, t=threadIdx.x;
  float acc=0.f;
#pragma unroll
  for(int ks=0;ks<8;ks++) acc+=part[(ks*32+b)*128+t];
  __shared__ float buf[128];
  float a=alpha[b*128+t];
  buf[t]=a*acc; __syncthreads();
  for(int off=64;off;off>>=1){ if(t<off) buf[t]+=buf[t+off]; __syncthreads(); }
  ds[b*128+t]=a*(acc-buf[0]);
}

// ---------- dfeat (S1, dz computed in-staging) + fused epilogue ----------
__global__ void __launch_bounds__(256) k_dfeat(
    const float* __restrict__ Wa, const float* __restrict__ att,
    const float* __restrict__ va, const float* __restrict__ ds,
    const float* __restrict__ feat, const float* __restrict__ alpha,
    const float* __restrict__ dMu, const float* __restrict__ dE2,
    float* __restrict__ dout3)
{
  constexpr int LDA=132, LDB=132;
  __shared__ float As[32*LDA];
  __shared__ float Bs[32*LDB];
  __shared__ float al[128], vs[128], dsv[128];
  const int d0=blockIdx.x*128, b=blockIdx.y;
  const int tid=threadIdx.x, wid=tid>>5, lane=tid&31;
  const int gid=lane>>2, tig=lane&3;
  const int m0=(wid&3)*32, n0=(wid>>2)*64;
  if(tid<128){
    al[tid]=alpha[b*128+tid];
    vs[tid]=va[tid];
    dsv[tid]=ds[b*128+tid];
  }
  float acc[2][8][4];
#pragma unroll
  for(int a=0;a<2;a++)
#pragma unroll
  for(int bq=0;bq<8;bq++)
#pragma unroll
  for(int c=0;c<4;c++) acc[a][bq][c]=0.f;

  for(int k0=0;k0<128;k0+=32){
    __syncthreads();
    for(int idx=tid; idx<4096; idx+=256){
      int kk=idx>>7, dd=idx&127;
      As[kk*LDA+dd]=to_tf32(Wa[(long)(k0+kk)*4096+d0+dd]);
    }
    for(int idx=tid; idx<4096; idx+=256){
      int kk=idx>>7, t=idx&127;
      int h=k0+kk;
      float a=att[((long)b*128+h)*128+t];
      float dzv=vs[h]*dsv[t]*(1.f-a*a);
      Bs[kk*LDB+t]=to_tf32(dzv);
    }
    __syncthreads();
#pragma unroll
    for(int kc=0;kc<4;kc++){
      const int kb=kc*8;
      unsigned bh[8][2];
#pragma unroll
      for(int f=0;f<8;f++){
        bh[f][0]=__float_as_uint(Bs[(kb+tig)*LDB + n0+f*8+gid]);
        bh[f][1]=__float_as_uint(Bs[(kb+tig+4)*LDB + n0+f*8+gid]);
      }
#pragma unroll
      for(int mf=0;mf<2;mf++){
        unsigned a0=__float_as_uint(As[(kb+tig)*LDA + m0+mf*16+gid]);
        unsigned a1=__float_as_uint(As[(kb+tig)*LDA + m0+mf*16+gid+8]);
        unsigned a2=__float_as_uint(As[(kb+tig+4)*LDA + m0+mf*16+gid]);
        unsigned a3=__float_as_uint(As[(kb+tig+4)*LDA + m0+mf*16+gid+8]);
#pragma unroll
        for(int f=0;f<8;f++)
          mma_tf32(acc[mf][f], a0,a1,a2,a3, bh[f][0],bh[f][1]);
      }
    }
  }
#pragma unroll
  for(int mf=0;mf<2;mf++){
    int dA=d0+m0+mf*16+gid, dB=dA+8;
    float dmA=dMu[(long)b*4096+dA], deA=dE2[(long)b*4096+dA];
    float dmB=dMu[(long)b*4096+dB], deB=dE2[(long)b*4096+dB];
#pragma unroll
    for(int f=0;f<8;f++){
      int t=n0+f*8+tig*2;
      long fiA=((long)b*4096+dA)*128+t;
      long fiB=((long)b*4096+dB)*128+t;
      float2 fvA=*(const float2*)&feat[fiA];
      float2 fvB=*(const float2*)&feat[fiB];
      float2 rA, rB;
      rA.x = fvA.x>0.f? (acc[mf][f][0]+al[t]*(dmA+2.f*deA*fvA.x)) : 0.f;
      rA.y = fvA.y>0.f? (acc[mf][f][1]+al[t+1]*(dmA+2.f*deA*fvA.y)) : 0.f;
      rB.x = fvB.x>0.f? (acc[mf][f][2]+al[t]*(dmB+2.f*deB*fvB.x)) : 0.f;
      rB.y = fvB.y>0.f? (acc[mf][f][3]+al[t+1]*(dmB+2.f*deB*fvB.y)) : 0.f;
      *(float2*)&dout3[fiA]=rA;
      *(float2*)&dout3[fiB]=rB;
    }
  }
}

// ---------- row/col stats ----------
__global__ void k_rowstats(const float* __restrict__ fam,const float* __restrict__ x,
    float* __restrict__ cm,float* __restrict__ meanT)
{
  int w=(blockIdx.x*blockDim.x+threadIdx.x)>>5, lane=threadIdx.x&31;
  if(w>=4096) return;
  const float* fr=fam+(long)w*1024; const float* xr=x+(long)w*1024;
  float m=-1e30f, s=0.f;
  for(int t=lane;t<1024;t+=32){ m=fmaxf(m,fr[t]); s+=xr[t]; }
  for(int o=16;o;o>>=1){ m=fmaxf(m,__shfl_down_sync(~0u,m,o)); s+=__shfl_down_sync(~0u,s,o); }
  if(!lane){ cm[w]=m; meanT[w]=s*(1.f/1024.f); }
}
__global__ void k_colstats(const float* __restrict__ fam,const float* __restrict__ x,
    float* __restrict__ tm,float* __restrict__ meanF)
{
  int i=blockIdx.x*256+threadIdx.x; if(i>=32768) return;
  int b=i>>10, t=i&1023;
  const float* fb=fam+(long)b*131072+t; const float* xb=x+(long)b*131072+t;
  float m=-1e30f, s=0.f;
#pragma unroll 4
  for(int f=0;f<128;f++){ m=fmaxf(m,fb[f*1024]); s+=xb[f*1024]; }
  tm[i]=m; meanF[i]=s*(1.f/128.f);
}

// ---------- bitonic argsort ----------
template<int N>
__global__ void k_sort(const float* __restrict__ vals, int* __restrict__ idxout)
{
  __shared__ unsigned long long key[N];
  const int b=blockIdx.x, tid=threadIdx.x, TH=N/2;
  for(int i=tid;i<N;i+=TH){
    unsigned u=__float_as_uint(vals[b*N+i]);
    u = (u&0x80000000u)? ~u : (u|0x80000000u);
    key[i]=((unsigned long long)(~u)<<32)|(unsigned)i;
  }
  __syncthreads();
  for(int k=2;k<=N;k<<=1)
    for(int j=k>>1;j;j>>=1){
      for(int i=tid;i<N;i+=TH){
        int ixj=i^j;
        if(ixj>i){
          bool up=((i&k)==0);
          unsigned long long a=key[i],c=key[ixj];
          if((a>c)==up){ key[i]=c; key[ixj]=a; }
        }
      }
      __syncthreads();
    }
  for(int i=tid;i<128;i+=TH) idxout[b*128+i]=(int)(key[i]&0xFFFFFFFFu);
}

// ---------- RFM scan (parallel init) + mask prefixes ----------
__global__ void k_rfm(const int* __restrict__ sc,const int* __restrict__ st,
    const int* __restrict__ mask_t,const int* __restrict__ s_t,
    const int* __restrict__ is_train,int* __restrict__ rstep,int* __restrict__ cstep,
    int* __restrict__ rowp,int* __restrict__ colp)
{
  const int b=blockIdx.x, t=threadIdx.x;
  int* rs=rstep+b*128; int* cs=cstep+b*1024;
  rs[t]=-1;
  for(int i=t;i<1024;i+=128) cs[i]=-1;
  __syncthreads();
  if(t==0){
    bool train = !(is_train && is_train[0]==0);
    if(train){
      int cnt=0;
      for(int s=0;s<128 && cnt<3;s++){
        int pc=sc[b*128+s], pt=st[b*128+s];
        if(rs[pc]!=-1||cs[pt]!=-1) continue;
        int mt=mask_t[b*128+s], ss=s_t[b*128+s];
        rs[pc]=s;
        int l=pt-ss; if(l<0)l=0;
        int r=pt+mt-ss; if(r>1024)r=1024;
        for(int tt=l;tt<r;tt++) cs[tt]=s;
        cnt++;
      }
    }
    int acc=0;
    rowp[b*129]=0;
    for(int i=0;i<128;i++){ acc += (rs[i]>=0); rowp[b*129+i+1]=acc; }
    acc=0;
    colp[b*1025]=0;
    for(int i=0;i<1024;i++){ acc += (cs[i]>=0); colp[b*1025+i+1]=acc; }
  }
}

// ---------- apply mask ----------
__global__ void k_apply(const float* __restrict__ x,const int* __restrict__ rstep,
    const int* __restrict__ cstep,const float* __restrict__ meanT,
    const float* __restrict__ meanF,float* __restrict__ xm)
{
  long i=(long)blockIdx.x*256+threadIdx.x; if(i>=4194304) return;
  int t=(int)(i&1023); int f=(int)((i>>10)&127); int b=(int)(i>>17);
  int rs=rstep[b*128+f], cs=cstep[b*1024+t];
  float v;
  if(rs<0&&cs<0) v=x[i];
  else v=(cs>=rs)? meanT[b*128+f] : meanF[b*1024+t];
  xm[i]=v;
}

// ---------- emb head ----------
__global__ void k_cat(const float* __restrict__ mu,const float* __restrict__ m2,
                      float* __restrict__ cat)
{
  int i=blockIdx.x*256+threadIdx.x; if(i>=131072) return;
  int b=i>>12, d=i&4095;
  float m=mu[i];
  cat[(long)b*8192+d]=m;
  cat[(long)b*8192+4096+d]=sqrtf(fmaxf(m2[i]-m*m,1e-5f));
}
__global__ void __launch_bounds__(256) k_embp(
    const float* __restrict__ cat,const float* __restrict__ We,
    float* __restrict__ part)
{
  __shared__ float cs[32][64];
  const int ks=blockIdx.x, j=threadIdx.x;
  for(int idx=j; idx<32*64; idx+=256){
    int b=idx>>6, ii=idx&63;
    cs[b][ii]=cat[(long)b*8192 + ks*64 + ii];
  }
  __syncthreads();
  float acc[32];
#pragma unroll
  for(int b=0;b<32;b++) acc[b]=0.f;
  for(int ii=0;ii<64;ii++){
    float w=We[((long)ks*64+ii)*256+j];
#pragma unroll
    for(int b=0;b<32;b++) acc[b]+=cs[b][ii]*w;
  }
#pragma unroll
  for(int b=0;b<32;b++) part[((long)ks*32+b)*256+j]=acc[b];
}
__global__ void __launch_bounds__(256) k_embf(
    const float* __restrict__ part,const float* __restrict__ be,
    const float* __restrict__ Wc,const float* __restrict__ bc,
    float* __restrict__ out)
{
  const int b=blockIdx.x, j=threadIdx.x;
  float s=be[j];
  for(int ks=0;ks<128;ks++) s+=part[((long)ks*32+b)*256+j];
  __shared__ float es[256];
  es[j]=s; __syncthreads();
  if(j<2){
    float acc=bc[j];
    for(int q=0;q<256;q++) acc+=es[q]*Wc[q*2+j];
    out[b*2+j]=acc;
  }
}

// ---------- host ----------
static void run_tail(const float* h3,const float* Wa,const float* ba,const float* va,
                     float* attp,float* att,float* alpha,float* mu,float* m2)
{
  k_attp<<<dim3(8,32),256>>>(Wa,h3,attp);
  k_attf<<<2048,256>>>(attp,ba,att);
  k_salpha<<<32,128>>>(att,va,alpha);
  k_mustats<<<16384,256>>>(h3,alpha,mu,m2);
}

extern "C" void kernel_launch(void* const* d_in,const int* in_sizes,int n_in,
                              void* d_out,int out_size)
{
  const float* x =(const float*)d_in[0];
  const float* W1=(const float*)d_in[1]; const float* b1=(const float*)d_in[2];
  const float* W2=(const float*)d_in[3]; const float* b2=(const float*)d_in[4];
  const float* W3=(const float*)d_in[5]; const float* b3=(const float*)d_in[6];
  const float* Wa=(const float*)d_in[7]; const float* ba=(const float*)d_in[8];
  const float* va=(const float*)d_in[9];
  const float* We=(const float*)d_in[10]; const float* be=(const float*)d_in[11];
  const float* Wc=(const float*)d_in[12]; const float* bc=(const float*)d_in[13];
  const int* mask_t=(const int*)d_in[14]; const int* s_t=(const int*)d_in[15];
  const int* is_train = (n_in>16)? (const int*)d_in[16] : nullptr;
  float* out=(float*)d_out;

  float *h1,*h2,*h3,*d1,*d2,*d3,*fam,*xm,*att,*attp,*alpha,*ds,*dap,*mu,*m2,*dMu,*dE2,*gvec;
  float *cat,*ep,*cm,*tm,*meanT,*meanF,*wtf2,*wtb2,*wtf3,*wtb3;
  int *sc,*st,*rstep,*cstep,*rowp,*colp;
  cudaGetSymbolAddress((void**)&h1,g_h1);   cudaGetSymbolAddress((void**)&h2,g_h2);
  cudaGetSymbolAddress((void**)&h3,g_h3);   cudaGetSymbolAddress((void**)&d1,g_d1);
  cudaGetSymbolAddress((void**)&d2,g_d2);   cudaGetSymbolAddress((void**)&d3,g_d3);
  cudaGetSymbolAddress((void**)&fam,g_fam); cudaGetSymbolAddress((void**)&xm,g_xm);
  cudaGetSymbolAddress((void**)&att,g_att); cudaGetSymbolAddress((void**)&attp,g_attp);
  cudaGetSymbolAddress((void**)&alpha,g_alpha); cudaGetSymbolAddress((void**)&ds,g_dsb);
  cudaGetSymbolAddress((void**)&dap,g_dap);
  cudaGetSymbolAddress((void**)&mu,g_mu);   cudaGetSymbolAddress((void**)&m2,g_m2);
  cudaGetSymbolAddress((void**)&dMu,g_dMu); cudaGetSymbolAddress((void**)&dE2,g_dE2);
  cudaGetSymbolAddress((void**)&gvec,g_gvec);
  cudaGetSymbolAddress((void**)&cat,g_cat); cudaGetSymbolAddress((void**)&ep,g_ep);
  cudaGetSymbolAddress((void**)&cm,g_cm);   cudaGetSymbolAddress((void**)&tm,g_tm);
  cudaGetSymbolAddress((void**)&meanT,g_meanT); cudaGetSymbolAddress((void**)&meanF,g_meanF);
  cudaGetSymbolAddress((void**)&sc,g_sc);   cudaGetSymbolAddress((void**)&st,g_st);
  cudaGetSymbolAddress((void**)&rstep,g_rstep); cudaGetSymbolAddress((void**)&cstep,g_cstep);
  cudaGetSymbolAddress((void**)&rowp,g_rowp);   cudaGetSymbolAddress((void**)&colp,g_colp);
  cudaGetSymbolAddress((void**)&wtf2,g_wtf2); cudaGetSymbolAddress((void**)&wtb2,g_wtb2);
  cudaGetSymbolAddress((void**)&wtf3,g_wtf3); cudaGetSymbolAddress((void**)&wtb3,g_wtb3);

  const int SMEM1 = 120*136*4;
  const int SMEM3 = 168*136*4;
  cudaFuncSetAttribute(k_cmma<64,128,64,512,1>,  cudaFuncAttributeMaxDynamicSharedMemorySize, SMEM1);
  cudaFuncSetAttribute(k_cmma<64,128,64,512,3>,  cudaFuncAttributeMaxDynamicSharedMemorySize, SMEM3);
  cudaFuncSetAttribute(k_cmma<128,256,32,256,1>, cudaFuncAttributeMaxDynamicSharedMemorySize, SMEM1);
  cudaFuncSetAttribute(k_cmma<128,256,32,256,3>, cudaFuncAttributeMaxDynamicSharedMemorySize, SMEM3);

  // prep
  k_wt<<<288,256>>>(W2,wtf2,wtb2,64,128);
  k_wt<<<1152,256>>>(W3,wtf3,wtb3,128,256);
  k_gvec<<<1024,256>>>(We,Wc,gvec);
  // pass 1: forward convs 3xTF32 (argsort-critical); conv1 compiled WITHOUT skip
  k_conv1<0><<<dim3(8,64,32),256>>>(x,W1,b1,h1,nullptr,nullptr);
  k_cmma<64,128,64,512,3><<<dim3(2,32,32),256,SMEM3>>>(h1,wtf2,b2,h2);
  k_cmma<128,256,32,256,3><<<dim3(2,16,32),256,SMEM3>>>(h2,wtf3,b3,h3);
  run_tail(h3,Wa,ba,va,attp,att,alpha,mu,m2);
  // backward to input: single-tf32
  k_dcoef<<<512,256>>>(mu,m2,gvec,dMu,dE2);
  k_dalp<<<dim3(8,32),128>>>(h3,dMu,dE2,dap);
  k_dalf<<<32,128>>>(dap,alpha,ds);
  k_dfeat<<<dim3(32,32),256>>>(Wa,att,va,ds,h3,alpha,dMu,dE2,d3);
  k_cbmma<128,256,16,128,128><<<dim3(2,32,32),256>>>(d3,wtb3,h2,d2);
  k_cbmma<64,128,32,256,256><<<dim3(2,64,32),256>>>(d2,wtb2,h1,d1);
  k_bwd1<<<dim3(2,64,32),256>>>(d1,W1,fam);
  // masking
  k_rowstats<<<512,256>>>(fam,x,cm,meanT);
  k_colstats<<<128,256>>>(fam,x,tm,meanF);
  k_sort<128><<<32,64>>>(cm,sc);
  k_sort<1024><<<32,512>>>(tm,st);
  k_rfm<<<32,128>>>(sc,st,mask_t,s_t,is_train,rstep,cstep,rowp,colp);
  k_apply<<<16384,256>>>(x,rstep,cstep,meanT,meanF,xm);
  // pass 2 (single tf32); conv1 compiled WITH skip, updates h1 in place
  k_conv1<1><<<dim3(8,64,32),256>>>(xm,W1,b1,h1,rowp,colp);
  k_cmma<64,128,64,512,1><<<dim3(2,32,32),256,SMEM1>>>(h1,wtf2,b2,h2);
  k_cmma<128,256,32,256,1><<<dim3(2,16,32),256,SMEM1>>>(h2,wtf3,b3,h3);
  run_tail(h3,Wa,ba,va,attp,att,alpha,mu,m2);
  k_cat<<<512,256>>>(mu,m2,cat);
  k_embp<<<128,256>>>(cat,We,ep);
  k_embf<<<32,256>>>(ep,be,Wc,bc,out);
}

// round 17
// speedup vs baseline: 1.0201x; 1.0021x over previous
#include <cuda_runtime.h>
#include <math.h>

// ---------- static scratch ----------
__device__ float g_h1[67108864];
__device__ float g_h2[33554432];
__device__ float g_h3[16777216];
__device__ float g_d1[67108864];
__device__ float g_d2[33554432];
__device__ float g_d3[16777216];
__device__ float g_fam[4194304];
__device__ float g_xm[4194304];
__device__ float g_att[524288];
__device__ float g_attp[4194304];
__device__ float g_alpha[4096];
__device__ float g_dsb[4096];
__device__ float g_dap[32768];
__device__ float g_mu[131072];
__device__ float g_m2[131072];
__device__ float g_dMu[131072];
__device__ float g_dE2[131072];
__device__ float g_gvec[8192];
__device__ float g_cat[262144];
__device__ float g_ep[1048576];
__device__ float g_cm[4096];
__device__ float g_tm[32768];
__device__ float g_meanT[4096];
__device__ float g_meanF[32768];
__device__ int   g_sc[4096];
__device__ int   g_st[4096];
__device__ int   g_rstep[4096];
__device__ int   g_cstep[32768];
__device__ int   g_rowp[4128];
__device__ int   g_colp[32800];
__device__ float g_wtf2[73728];
__device__ float g_wtb2[73728];
__device__ float g_wtf3[294912];
__device__ float g_wtb3[294912];

// ---------- weight transposes ----------
__global__ void k_wt(const float* __restrict__ W, float* __restrict__ WTf,
                     float* __restrict__ WTb, int CIN, int COUT)
{
  int idx=blockIdx.x*256+threadIdx.x;
  int tot=CIN*COUT*9; if(idx>=tot) return;
  int k=idx%9, c=(idx/9)%CIN, o=idx/(9*CIN);
  float v=W[idx];
  int rf=(c>>3)*72 + k*8 + (c&7);
  WTf[(long)rf*COUT+o]=v;
  int rb=(o>>3)*72 + k*8 + (o&7);
  WTb[(long)rb*CIN+c]=v;
}

// ---------- conv1 fwd (compile-time skip variant) ----------
template<int SKIP>
__global__ void __launch_bounds__(256) k_conv1(
    const float* __restrict__ in, const float* __restrict__ W,
    const float* __restrict__ bias, float* __restrict__ out,
    const int* __restrict__ rowp, const int* __restrict__ colp)
{
  __shared__ __align__(16) float ins[3][132];
  __shared__ __align__(16) float ws[9][64];
  __shared__ float bs[64];
  const int n=blockIdx.z, i=blockIdx.y, j0=blockIdx.x*64;
  if(SKIP){
    int r0=2*i, r1=2*i+3; if(r1>128) r1=128;
    int c0=2*j0, c1=2*j0+130; if(c1>1024) c1=1024;
    if(rowp[n*129+r1]==rowp[n*129+r0] && colp[n*1025+c1]==colp[n*1025+c0]) return;
  }
  const int tid=threadIdx.x, jt=tid&15, og=tid>>4;
  for(int idx=tid; idx<576; idx+=256){
    int o=idx/9, k=idx%9;
    ws[k][o]=W[idx];
  }
  if(tid<64) bs[tid]=bias[tid];
  for(int idx=tid; idx<3*130; idx+=256){
    int r=idx/130, col=idx%130;
    int gx=2*i+r, gy=2*j0+col;
    float v=0.f;
    if(gx<128 && gy<1024) v=in[((long)n*128+gx)*1024+gy];
    ins[r][col]=v;
  }
  __syncthreads();
  float acc[4][4];
#pragma unroll
  for(int o=0;o<4;o++)
#pragma unroll
  for(int e=0;e<4;e++) acc[o][e]=0.f;
#pragma unroll
  for(int r=0;r<3;r++){
    float v[9];
    *(float4*)v     = *(float4*)&ins[r][8*jt];
    *(float4*)(v+4) = *(float4*)&ins[r][8*jt+4];
    v[8]            = ins[r][8*jt+8];
#pragma unroll
    for(int kj=0;kj<3;kj++){
      float w[4];
      *(float4*)w = *(float4*)&ws[r*3+kj][og*4];
#pragma unroll
      for(int oo=0;oo<4;oo++)
#pragma unroll
      for(int e=0;e<4;e++)
        acc[oo][e]+=w[oo]*v[2*e+kj];
    }
  }
#pragma unroll
  for(int oo=0;oo<4;oo++){
    int o=og*4+oo;
    float bb=bs[o];
    float4 r;
    r.x=fmaxf(acc[oo][0]+bb,0.f); r.y=fmaxf(acc[oo][1]+bb,0.f);
    r.z=fmaxf(acc[oo][2]+bb,0.f); r.w=fmaxf(acc[oo][3]+bb,0.f);
    *(float4*)&out[(((long)n*64+o)*64+i)*512 + j0 + 4*jt]=r;
  }
}

// ---------- tf32 helpers ----------
__device__ __forceinline__ float to_tf32(float v){
  unsigned r; asm("cvt.rna.tf32.f32 %0, %1;" : "=r"(r) : "f"(v));
  return __uint_as_float(r);
}
__device__ __forceinline__ void mma_tf32(float* c4,
    unsigned a0,unsigned a1,unsigned a2,unsigned a3,unsigned b0,unsigned b1){
  asm volatile(
    "mma.sync.aligned.m16n8k8.row.col.f32.tf32.tf32.f32 "
    "{%0,%1,%2,%3},{%4,%5,%6,%7},{%8,%9},{%0,%1,%2,%3};"
    : "+f"(c4[0]),"+f"(c4[1]),"+f"(c4[2]),"+f"(c4[3])
    : "r"(a0),"r"(a1),"r"(a2),"r"(a3),"r"(b0),"r"(b1));
}

// ---------- tf32 mma conv fwd; staging-side cvt ----------
template<int CIN,int COUT,int HIN,int WIN,int SPLIT>
__global__ void __launch_bounds__(256,2) k_cmma(
    const float* __restrict__ in, const float* __restrict__ WT,
    const float* __restrict__ bias, float* __restrict__ out)
{
  constexpr int HOUT=HIN/2, WOUT=WIN/2;
  constexpr int NJT=WOUT/128;
  constexpr int LD=136;
  constexpr int WOFF=(SPLIT==3)?96:48;
  extern __shared__ float sm[];
  float* evh = sm;
  float* odh = sm + 24*LD;
  float* evl = sm + 48*LD;
  float* odl = sm + 72*LD;
  float* ws  = sm + WOFF*LD;
  const int n=blockIdx.z, i=blockIdx.y;
  const int jt_=blockIdx.x%NJT, ot=blockIdx.x/NJT;
  const int j0=jt_*128, o0=ot*128;
  const int tid=threadIdx.x, wid=tid>>5, lane=tid&31;
  const int gid=lane>>2, tig=lane&3;
  const int m0=(wid&3)*32, n0w=(wid>>2)*64;
  float acc[2][8][4];
#pragma unroll
  for(int a=0;a<2;a++)
#pragma unroll
  for(int b=0;b<8;b++)
#pragma unroll
  for(int c=0;c<4;c++) acc[a][b][c]=0.f;

  for(int c0=0;c0<CIN;c0+=8){
    __syncthreads();
    for(int idx=tid; idx<8*3*129; idx+=256){
      int c=idx/387, rem=idx%387, r=rem/129, p=rem%129;
      int gx=2*i+r, gy=2*j0+2*p;
      float a=0.f,bv=0.f;
      if(gx<HIN && gy<WIN){
        const float2 s=*(const float2*)&in[(((long)n*CIN+c0+c)*HIN+gx)*WIN+gy];
        a=s.x; bv=s.y;
      }
      float ah=to_tf32(a), bh=to_tf32(bv);
      evh[(c*3+r)*LD+p]=ah;
      odh[(c*3+r)*LD+p]=bh;
      if(SPLIT==3){
        evl[(c*3+r)*LD+p]=to_tf32(a-ah);
        odl[(c*3+r)*LD+p]=to_tf32(bv-bh);
      }
    }
    {
      const float* wsrc = WT + (long)(c0>>3)*72*COUT + o0;
      for(int idx=tid; idx<72*32; idx+=256){
        int kk=idx>>5, o4=(idx&31)*4;
        float4 v=*(const float4*)&wsrc[(long)kk*COUT + o4];
        if(SPLIT==1){ v.x=to_tf32(v.x); v.y=to_tf32(v.y); v.z=to_tf32(v.z); v.w=to_tf32(v.w); }
        *(float4*)&ws[kk*LD + o4]=v;
      }
    }
    __syncthreads();
#pragma unroll
    for(int kc=0;kc<9;kc++){
      const int r=kc/3, kj=kc%3;
      const float* srch = (kj==1)? odh : evh;
      const float* srcl = (kj==1)? odl : evl;
      const int co = (kj==2)? 1:0;
      unsigned bh[8][2], bl[8][2];
#pragma unroll
      for(int f=0;f<8;f++){
        int i0=(tig*3+r)*LD + n0w + f*8 + gid + co;
        int i1=((tig+4)*3+r)*LD + n0w + f*8 + gid + co;
        bh[f][0]=__float_as_uint(srch[i0]);
        bh[f][1]=__float_as_uint(srch[i1]);
        if(SPLIT==3){
          bl[f][0]=__float_as_uint(srcl[i0]);
          bl[f][1]=__float_as_uint(srcl[i1]);
        }
      }
#pragma unroll
      for(int mf=0;mf<2;mf++){
        unsigned ah0,ah1,ah2,ah3,al0=0,al1=0,al2=0,al3=0;
        if(SPLIT==1){
          ah0=__float_as_uint(ws[(kc*8+tig)*LD + m0+mf*16+gid]);
          ah1=__float_as_uint(ws[(kc*8+tig)*LD + m0+mf*16+gid+8]);
          ah2=__float_as_uint(ws[(kc*8+tig+4)*LD + m0+mf*16+gid]);
          ah3=__float_as_uint(ws[(kc*8+tig+4)*LD + m0+mf*16+gid+8]);
        }else{
          float w0=ws[(kc*8+tig)*LD + m0+mf*16+gid];
          float w1=ws[(kc*8+tig)*LD + m0+mf*16+gid+8];
          float w2=ws[(kc*8+tig+4)*LD + m0+mf*16+gid];
          float w3=ws[(kc*8+tig+4)*LD + m0+mf*16+gid+8];
          float h0=to_tf32(w0),h1=to_tf32(w1),h2=to_tf32(w2),h3=to_tf32(w3);
          ah0=__float_as_uint(h0); ah1=__float_as_uint(h1);
          ah2=__float_as_uint(h2); ah3=__float_as_uint(h3);
          al0=__float_as_uint(to_tf32(w0-h0)); al1=__float_as_uint(to_tf32(w1-h1));
          al2=__float_as_uint(to_tf32(w2-h2)); al3=__float_as_uint(to_tf32(w3-h3));
        }
#pragma unroll
        for(int f=0;f<8;f++){
          mma_tf32(acc[mf][f], ah0,ah1,ah2,ah3, bh[f][0],bh[f][1]);
          if(SPLIT==3){
            mma_tf32(acc[mf][f], ah0,ah1,ah2,ah3, bl[f][0],bl[f][1]);
            mma_tf32(acc[mf][f], al0,al1,al2,al3, bh[f][0],bh[f][1]);
          }
        }
      }
    }
  }
#pragma unroll
  for(int mf=0;mf<2;mf++){
    int oA=o0+m0+mf*16+gid, oB=oA+8;
    float bA=bias[oA], bB=bias[oB];
#pragma unroll
    for(int f=0;f<8;f++){
      int jj=j0 + n0w + f*8 + tig*2;
      long baseA=(((long)n*COUT+oA)*HOUT+i)*WOUT + jj;
      long baseB=(((long)n*COUT+oB)*HOUT+i)*WOUT + jj;
      float2 rA, rB;
      rA.x=fmaxf(acc[mf][f][0]+bA,0.f); rA.y=fmaxf(acc[mf][f][1]+bA,0.f);
      rB.x=fmaxf(acc[mf][f][2]+bB,0.f); rB.y=fmaxf(acc[mf][f][3]+bB,0.f);
      *(float2*)&out[baseA]=rA;
      *(float2*)&out[baseB]=rB;
    }
  }
}

// ---------- tf32 mma transposed-conv bwd (S1, staging-side cvt) ----------
template<int CIN,int COUT,int HOUT,int WOUT,int NT>
__global__ void __launch_bounds__(256,2) k_cbmma(
    const float* __restrict__ dout, const float* __restrict__ WT,
    const float* __restrict__ act, float* __restrict__ din)
{
  constexpr int HIN=2*HOUT, WIN=2*WOUT;
  constexpr int LDW=CIN+8, LDD=NT/2+4, JL=NT/2+2;
  constexpr int NW_M=CIN/32;
  __shared__ float ws[72*LDW];
  __shared__ float dsA[8*LDD];
  __shared__ float dsB[8*LDD];
  const int n=blockIdx.z, x=blockIdx.y, y0=blockIdx.x*NT;
  const int tid=threadIdx.x, wid=tid>>5, lane=tid&31;
  const int gid=lane>>2, tig=lane&3;
  const int m0=(wid%NW_M)*32, n0=(wid/NW_M)*64;
  const bool xe=((x&1)==0);
  const int iA = xe ? (x>>1) : ((x-1)>>1);
  const int iB = (x>>1)-1;
  const bool hasB = xe && iB>=0;
  const int jb = y0/2 - 1;
  float acc_e[2][4][4], acc_o[2][4][4];
#pragma unroll
  for(int a=0;a<2;a++)
#pragma unroll
  for(int b=0;b<4;b++)
#pragma unroll
  for(int c=0;c<4;c++){acc_e[a][b][c]=0.f; acc_o[a][b][c]=0.f;}

  for(int o0=0;o0<COUT;o0+=8){
    __syncthreads();
    {
      const float* wsrc = WT + (long)(o0>>3)*72*CIN;
      for(int idx=tid; idx<72*(CIN/4); idx+=256){
        int r=idx/(CIN/4), c4=(idx%(CIN/4))*4;
        float4 v=*(const float4*)&wsrc[(long)r*CIN+c4];
        v.x=to_tf32(v.x); v.y=to_tf32(v.y); v.z=to_tf32(v.z); v.w=to_tf32(v.w);
        *(float4*)&ws[r*LDW+c4]=v;
      }
    }
    for(int idx=tid; idx<8*JL; idx+=256){
      int o=idx/JL, jl=idx%JL; int j=jb+jl;
      float a=0.f,bv=0.f;
      if(j>=0 && j<WOUT){
        long base=((long)n*COUT+o0+o)*HOUT;
        a = dout[(base+iA)*WOUT+j];
        if(hasB) bv = dout[(base+iB)*WOUT+j];
      }
      dsA[o*LDD+jl]=to_tf32(a); dsB[o*LDD+jl]=to_tf32(bv);
    }
    __syncthreads();

    auto proc = [&](const float* ds, const int tapBase){
      unsigned b1[4][2], b0[4][2];
#pragma unroll
      for(int f=0;f<4;f++){
        int cbase = n0/2 + f*8 + gid;
        b1[f][0]=__float_as_uint(ds[tig*LDD + cbase + 1]);
        b1[f][1]=__float_as_uint(ds[(tig+4)*LDD + cbase + 1]);
        b0[f][0]=__float_as_uint(ds[tig*LDD + cbase]);
        b0[f][1]=__float_as_uint(ds[(tig+4)*LDD + cbase]);
      }
#pragma unroll
      for(int kj=0;kj<3;kj++){
        const int tap=tapBase+kj;
#pragma unroll
        for(int mf=0;mf<2;mf++){
          unsigned a0=__float_as_uint(ws[(tap*8+tig)*LDW + m0+mf*16+gid]);
          unsigned a1=__float_as_uint(ws[(tap*8+tig)*LDW + m0+mf*16+gid+8]);
          unsigned a2=__float_as_uint(ws[(tap*8+tig+4)*LDW + m0+mf*16+gid]);
          unsigned a3=__float_as_uint(ws[(tap*8+tig+4)*LDW + m0+mf*16+gid+8]);
#pragma unroll
          for(int f=0;f<4;f++){
            float* c4 = (kj==1)? acc_o[mf][f] : acc_e[mf][f];
            const unsigned* bb = (kj==2)? b0[f] : b1[f];
            mma_tf32(c4, a0,a1,a2,a3, bb[0],bb[1]);
          }
        }
      }
    };
    proc(dsA, xe?0:3);
    if(hasB) proc(dsB, 6);
  }

#pragma unroll
  for(int mf=0;mf<2;mf++){
    int c0_=m0+mf*16+gid;
#pragma unroll
    for(int f=0;f<4;f++){
      int Y = y0 + n0 + 2*(f*8 + 2*tig);
      long b0i=(((long)n*CIN+c0_)*HIN+x)*WIN + Y;
      long b1i=(((long)n*CIN+c0_+8)*HIN+x)*WIN + Y;
      float2 m, r;
      m=*(const float2*)&act[b0i];
      r.x = m.x>0.f? acc_e[mf][f][0]:0.f; r.y = m.y>0.f? acc_o[mf][f][0]:0.f;
      *(float2*)&din[b0i]=r;
      m=*(const float2*)&act[b0i+2];
      r.x = m.x>0.f? acc_e[mf][f][1]:0.f; r.y = m.y>0.f? acc_o[mf][f][1]:0.f;
      *(float2*)&din[b0i+2]=r;
      m=*(const float2*)&act[b1i];
      r.x = m.x>0.f? acc_e[mf][f][2]:0.f; r.y = m.y>0.f? acc_o[mf][f][2]:0.f;
      *(float2*)&din[b1i]=r;
      m=*(const float2*)&act[b1i+2];
      r.x = m.x>0.f? acc_e[mf][f][3]:0.f; r.y = m.y>0.f? acc_o[mf][f][3]:0.f;
      *(float2*)&din[b1i+2]=r;
    }
  }
}

// ---------- conv1 data-grad -> |dx|, q-pair (rows 4p..4p+3 per block) ----------
__global__ void __launch_bounds__(256) k_bwd1(
    const float* __restrict__ dz1, const float* __restrict__ W1,
    float* __restrict__ fam)
{
  __shared__ float ws[576];
  __shared__ float dsm[8*3*260];
  const int n=blockIdx.z, p=blockIdx.y, y0=blockIdx.x*512;
  const int tid=threadIdx.x;
  for(int idx=tid; idx<576; idx+=256) ws[idx]=W1[idx];
  const bool has0=(p>0);
  const int jbase=y0/2-1;
  float a0=0.f,a1=0.f,a2=0.f,a3=0.f,a4=0.f,a5=0.f,a6=0.f,a7=0.f;
  for(int o0=0;o0<64;o0+=8){
    __syncthreads();
    for(int idx=tid; idx<8*3*260; idx+=256){
      int o=idx/780, rs=(idx/260)%3, jj=idx%260;
      int j=jbase+jj; int ir=2*p-1+rs;
      float v=0.f;
      if(j>=0 && j<512 && ir>=0)
        v=dz1[(((long)n*64+o0+o)*64+ir)*512+j];
      dsm[idx]=v;
    }
    __syncthreads();
#pragma unroll
    for(int o=0;o<8;o++){
      const float* wb=&ws[(o0+o)*9];
      float vm0=dsm[(o*3+0)*260+tid], v00=dsm[(o*3+0)*260+tid+1]; // row 2p-1
      float vm1=dsm[(o*3+1)*260+tid], v01=dsm[(o*3+1)*260+tid+1]; // row 2p
      float vm2=dsm[(o*3+2)*260+tid], v02=dsm[(o*3+2)*260+tid+1]; // row 2p+1
      // x=4p (q=2p): rowA=2p (ki0), rowB=2p-1 (ki2)
      a0+=wb[0]*v01+wb[2]*vm1; a1+=wb[1]*v01;
      if(has0){ a0+=wb[6]*v00+wb[8]*vm0; a1+=wb[7]*v00; }
      // x=4p+1: row 2p (ki1)
      a2+=wb[3]*v01+wb[5]*vm1; a3+=wb[4]*v01;
      // x=4p+2 (q=2p+1): rowA=2p+1 (ki0), rowB=2p (ki2) always present
      a4+=wb[0]*v02+wb[2]*vm2; a5+=wb[1]*v02;
      a4+=wb[6]*v01+wb[8]*vm1; a5+=wb[7]*v01;
      // x=4p+3: row 2p+1 (ki1)
      a6+=wb[3]*v02+wb[5]*vm2; a7+=wb[4]*v02;
    }
  }
  long base=((long)n*128+4*p)*1024 + y0 + 2*tid;
  fam[base]=fabsf(a0);        fam[base+1]=fabsf(a1);
  fam[base+1024]=fabsf(a2);   fam[base+1025]=fabsf(a3);
  fam[base+2048]=fabsf(a4);   fam[base+2049]=fabsf(a5);
  fam[base+3072]=fabsf(a6);   fam[base+3073]=fabsf(a7);
}

// ---------- att partial GEMM (S1, staging-side cvt) ----------
__global__ void __launch_bounds__(256) k_attp(
    const float* __restrict__ Wa, const float* __restrict__ feat,
    float* __restrict__ attp)
{
  constexpr int LDA=129, LDB=132;
  __shared__ float As[32*LDA];
  __shared__ float Bs[32*LDB];
  const int ks=blockIdx.x, b=blockIdx.y;
  const int tid=threadIdx.x, wid=tid>>5, lane=tid&31;
  const int gid=lane>>2, tig=lane&3;
  const int m0=(wid&3)*32, n0=(wid>>2)*64;
  const float* fb = feat + (long)b*524288;
  float acc[2][8][4];
#pragma unroll
  for(int a=0;a<2;a++)
#pragma unroll
  for(int bq=0;bq<8;bq++)
#pragma unroll
  for(int c=0;c<4;c++) acc[a][bq][c]=0.f;

  for(int k0=ks*512; k0<ks*512+512; k0+=32){
    __syncthreads();
    for(int idx=tid; idx<4096; idx+=256){
      int h=idx>>5, kk=idx&31;
      As[kk*LDA+h]=to_tf32(Wa[(long)h*4096+k0+kk]);
    }
    for(int idx=tid; idx<4096; idx+=256){
      int kk=idx>>7, t=idx&127;
      Bs[kk*LDB+t]=to_tf32(fb[(long)(k0+kk)*128+t]);
    }
    __syncthreads();
#pragma unroll
    for(int kc=0;kc<4;kc++){
      const int kb=kc*8;
      unsigned bh[8][2];
#pragma unroll
      for(int f=0;f<8;f++){
        bh[f][0]=__float_as_uint(Bs[(kb+tig)*LDB + n0+f*8+gid]);
        bh[f][1]=__float_as_uint(Bs[(kb+tig+4)*LDB + n0+f*8+gid]);
      }
#pragma unroll
      for(int mf=0;mf<2;mf++){
        unsigned a0=__float_as_uint(As[(kb+tig)*LDA + m0+mf*16+gid]);
        unsigned a1=__float_as_uint(As[(kb+tig)*LDA + m0+mf*16+gid+8]);
        unsigned a2=__float_as_uint(As[(kb+tig+4)*LDA + m0+mf*16+gid]);
        unsigned a3=__float_as_uint(As[(kb+tig+4)*LDA + m0+mf*16+gid+8]);
#pragma unroll
        for(int f=0;f<8;f++)
          mma_tf32(acc[mf][f], a0,a1,a2,a3, bh[f][0],bh[f][1]);
      }
    }
  }
#pragma unroll
  for(int mf=0;mf<2;mf++){
    int hA=m0+mf*16+gid, hB=hA+8;
#pragma unroll
    for(int f=0;f<8;f++){
      int t=n0+f*8+tig*2;
      float2 rA, rB;
      rA.x=acc[mf][f][0]; rA.y=acc[mf][f][1];
      rB.x=acc[mf][f][2]; rB.y=acc[mf][f][3];
      *(float2*)&attp[(long)ks*524288 + ((long)b*128+hA)*128+t]=rA;
      *(float2*)&attp[(long)ks*524288 + ((long)b*128+hB)*128+t]=rB;
    }
  }
}
__global__ void k_attf(const float* __restrict__ attp, const float* __restrict__ ba,
                       float* __restrict__ att)
{
  int i=blockIdx.x*256+threadIdx.x; if(i>=524288) return;
  int h=(i>>7)&127;
  float s=0.f;
#pragma unroll
  for(int ks=0;ks<8;ks++) s+=attp[(long)ks*524288+i];
  att[i]=tanhf(s+ba[h]);
}

// ---------- softmax ----------
__global__ void __launch_bounds__(128) k_salpha(
    const float* __restrict__ att, const float* __restrict__ va,
    float* __restrict__ alpha)
{
  __shared__ float vs[128], buf[128];
  const int b=blockIdx.x, t=threadIdx.x;
  vs[t]=va[t];
  __syncthreads();
  float s=0.f;
#pragma unroll 4
  for(int h=0;h<128;h++) s+=vs[h]*att[((long)b*128+h)*128+t];
  buf[t]=s; __syncthreads();
  for(int off=64;off;off>>=1){ if(t<off) buf[t]=fmaxf(buf[t],buf[t+off]); __syncthreads(); }
  float mx=buf[0]; __syncthreads();
  float e=expf(s-mx);
  buf[t]=e; __syncthreads();
  for(int off=64;off;off>>=1){ if(t<off) buf[t]+=buf[t+off]; __syncthreads(); }
  alpha[b*128+t]=e/buf[0];
}

// ---------- mu, m2 ----------
__global__ void k_mustats(const float* __restrict__ feat,
    const float* __restrict__ alpha, float* __restrict__ mu, float* __restrict__ m2)
{
  int w=(blockIdx.x*blockDim.x+threadIdx.x)>>5, lane=threadIdx.x&31;
  if(w>=131072) return;
  int b=w>>12;
  const float* fr=feat+(long)w*128;
  const float* ar=alpha+b*128;
  float s1=0.f,s2=0.f;
#pragma unroll
  for(int t=lane;t<128;t+=32){
    float a=ar[t], f=fr[t];
    s1+=a*f; s2+=a*f*f;
  }
  for(int o=16;o;o>>=1){ s1+=__shfl_down_sync(~0u,s1,o); s2+=__shfl_down_sync(~0u,s2,o); }
  if(!lane){ mu[w]=s1; m2[w]=s2; }
}

// ---------- gvec ----------
__global__ void k_gvec(const float* __restrict__ We,const float* __restrict__ Wc,
                       float* __restrict__ gvec)
{
  int w=(blockIdx.x*blockDim.x+threadIdx.x)>>5, lane=threadIdx.x&31;
  if(w>=8192) return;
  float s=0.f;
  for(int j=lane;j<256;j+=32) s+=We[(long)w*256+j]*(Wc[j*2+1]-Wc[j*2]);
  for(int o=16;o;o>>=1) s+=__shfl_down_sync(~0u,s,o);
  if(!lane) gvec[w]=s;
}

// ---------- dMu,dE2 ----------
__global__ void k_dcoef(const float* __restrict__ mu,const float* __restrict__ m2,
    const float* __restrict__ gvec, float* __restrict__ dMu,float* __restrict__ dE2)
{
  int i=blockIdx.x*256+threadIdx.x; if(i>=131072) return;
  int d=i&4095;
  float m=mu[i], v=m2[i]-m*m;
  float g2=gvec[4096+d];
  float dE=0.f, dM=gvec[d];
  if(v>1e-5f){ float sg=sqrtf(v); dE=0.5f*g2/sg; dM-=g2*m/sg; }
  dMu[i]=dM; dE2[i]=dE;
}

// ---------- dalpha ----------
__global__ void __launch_bounds__(128) k_dalp(
    const float* __restrict__ feat,const float* __restrict__ dMu,
    const float* __restrict__ dE2,float* __restrict__ part)
{
  const int ks=blockIdx.x, b=blockIdx.y, t=threadIdx.x;
  const float* fb=feat+(long)b*524288;
  const float* dm=dMu+b*4096; const float* de=dE2+b*4096;
  float acc=0.f;
  int d0=ks*512;
#pragma unroll 4
  for(int d=d0;d<d0+512;d++){
    float f=fb[(long)d*128+t];
    acc+=dm[d]*f+de[d]*f*f;
  }
  part[(ks*32+b)*128+t]=acc;
}
__global__ void __launch_bounds__(128) k_dalf(
    const float* __restrict__ part,const float* __restrict__ alpha,
    float* __restrict__ ds)
{
  const int b=blockIdx.x, t=threadIdx.x;
  float acc=0.f;
#pragma unroll
  for(int ks=0;ks<8;ks++) acc+=part[(ks*32+b)*128+t];
  __shared__ float buf[128];
  float a=alpha[b*128+t];
  buf[t]=a*acc; __syncthreads();
  for(int off=64;off;off>>=1){ if(t<off) buf[t]+=buf[t+off]; __syncthreads(); }
  ds[b*128+t]=a*(acc-buf[0]);
}

// ---------- dfeat (S1, dz computed in-staging) + fused epilogue ----------
__global__ void __launch_bounds__(256) k_dfeat(
    const float* __restrict__ Wa, const float* __restrict__ att,
    const float* __restrict__ va, const float* __restrict__ ds,
    const float* __restrict__ feat, const float* __restrict__ alpha,
    const float* __restrict__ dMu, const float* __restrict__ dE2,
    float* __restrict__ dout3)
{
  constexpr int LDA=132, LDB=132;
  __shared__ float As[32*LDA];
  __shared__ float Bs[32*LDB];
  __shared__ float al[128], vs[128], dsv[128];
  const int d0=blockIdx.x*128, b=blockIdx.y;
  const int tid=threadIdx.x, wid=tid>>5, lane=tid&31;
  const int gid=lane>>2, tig=lane&3;
  const int m0=(wid&3)*32, n0=(wid>>2)*64;
  if(tid<128){
    al[tid]=alpha[b*128+tid];
    vs[tid]=va[tid];
    dsv[tid]=ds[b*128+tid];
  }
  float acc[2][8][4];
#pragma unroll
  for(int a=0;a<2;a++)
#pragma unroll
  for(int bq=0;bq<8;bq++)
#pragma unroll
  for(int c=0;c<4;c++) acc[a][bq][c]=0.f;

  for(int k0=0;k0<128;k0+=32){
    __syncthreads();
    for(int idx=tid; idx<4096; idx+=256){
      int kk=idx>>7, dd=idx&127;
      As[kk*LDA+dd]=to_tf32(Wa[(long)(k0+kk)*4096+d0+dd]);
    }
    for(int idx=tid; idx<4096; idx+=256){
      int kk=idx>>7, t=idx&127;
      int h=k0+kk;
      float a=att[((long)b*128+h)*128+t];
      float dzv=vs[h]*dsv[t]*(1.f-a*a);
      Bs[kk*LDB+t]=to_tf32(dzv);
    }
    __syncthreads();
#pragma unroll
    for(int kc=0;kc<4;kc++){
      const int kb=kc*8;
      unsigned bh[8][2];
#pragma unroll
      for(int f=0;f<8;f++){
        bh[f][0]=__float_as_uint(Bs[(kb+tig)*LDB + n0+f*8+gid]);
        bh[f][1]=__float_as_uint(Bs[(kb+tig+4)*LDB + n0+f*8+gid]);
      }
#pragma unroll
      for(int mf=0;mf<2;mf++){
        unsigned a0=__float_as_uint(As[(kb+tig)*LDA + m0+mf*16+gid]);
        unsigned a1=__float_as_uint(As[(kb+tig)*LDA + m0+mf*16+gid+8]);
        unsigned a2=__float_as_uint(As[(kb+tig+4)*LDA + m0+mf*16+gid]);
        unsigned a3=__float_as_uint(As[(kb+tig+4)*LDA + m0+mf*16+gid+8]);
#pragma unroll
        for(int f=0;f<8;f++)
          mma_tf32(acc[mf][f], a0,a1,a2,a3, bh[f][0],bh[f][1]);
      }
    }
  }
#pragma unroll
  for(int mf=0;mf<2;mf++){
    int dA=d0+m0+mf*16+gid, dB=dA+8;
    float dmA=dMu[(long)b*4096+dA], deA=dE2[(long)b*4096+dA];
    float dmB=dMu[(long)b*4096+dB], deB=dE2[(long)b*4096+dB];
#pragma unroll
    for(int f=0;f<8;f++){
      int t=n0+f*8+tig*2;
      long fiA=((long)b*4096+dA)*128+t;
      long fiB=((long)b*4096+dB)*128+t;
      float2 fvA=*(const float2*)&feat[fiA];
      float2 fvB=*(const float2*)&feat[fiB];
      float2 rA, rB;
      rA.x = fvA.x>0.f? (acc[mf][f][0]+al[t]*(dmA+2.f*deA*fvA.x)) : 0.f;
      rA.y = fvA.y>0.f? (acc[mf][f][1]+al[t+1]*(dmA+2.f*deA*fvA.y)) : 0.f;
      rB.x = fvB.x>0.f? (acc[mf][f][2]+al[t]*(dmB+2.f*deB*fvB.x)) : 0.f;
      rB.y = fvB.y>0.f? (acc[mf][f][3]+al[t+1]*(dmB+2.f*deB*fvB.y)) : 0.f;
      *(float2*)&dout3[fiA]=rA;
      *(float2*)&dout3[fiB]=rB;
    }
  }
}

// ---------- row/col stats ----------
__global__ void k_rowstats(const float* __restrict__ fam,const float* __restrict__ x,
    float* __restrict__ cm,float* __restrict__ meanT)
{
  int w=(blockIdx.x*blockDim.x+threadIdx.x)>>5, lane=threadIdx.x&31;
  if(w>=4096) return;
  const float* fr=fam+(long)w*1024; const float* xr=x+(long)w*1024;
  float m=-1e30f, s=0.f;
  for(int t=lane;t<1024;t+=32){ m=fmaxf(m,fr[t]); s+=xr[t]; }
  for(int o=16;o;o>>=1){ m=fmaxf(m,__shfl_down_sync(~0u,m,o)); s+=__shfl_down_sync(~0u,s,o); }
  if(!lane){ cm[w]=m; meanT[w]=s*(1.f/1024.f); }
}
__global__ void k_colstats(const float* __restrict__ fam,const float* __restrict__ x,
    float* __restrict__ tm,float* __restrict__ meanF)
{
  int i=blockIdx.x*256+threadIdx.x; if(i>=32768) return;
  int b=i>>10, t=i&1023;
  const float* fb=fam+(long)b*131072+t; const float* xb=x+(long)b*131072+t;
  float m=-1e30f, s=0.f;
#pragma unroll 4
  for(int f=0;f<128;f++){ m=fmaxf(m,fb[f*1024]); s+=xb[f*1024]; }
  tm[i]=m; meanF[i]=s*(1.f/128.f);
}

// ---------- bitonic argsort ----------
template<int N>
__global__ void k_sort(const float* __restrict__ vals, int* __restrict__ idxout)
{
  __shared__ unsigned long long key[N];
  const int b=blockIdx.x, tid=threadIdx.x, TH=N/2;
  for(int i=tid;i<N;i+=TH){
    unsigned u=__float_as_uint(vals[b*N+i]);
    u = (u&0x80000000u)? ~u : (u|0x80000000u);
    key[i]=((unsigned long long)(~u)<<32)|(unsigned)i;
  }
  __syncthreads();
  for(int k=2;k<=N;k<<=1)
    for(int j=k>>1;j;j>>=1){
      for(int i=tid;i<N;i+=TH){
        int ixj=i^j;
        if(ixj>i){
          bool up=((i&k)==0);
          unsigned long long a=key[i],c=key[ixj];
          if((a>c)==up){ key[i]=c; key[ixj]=a; }
        }
      }
      __syncthreads();
    }
  for(int i=tid;i<128;i+=TH) idxout[b*128+i]=(int)(key[i]&0xFFFFFFFFu);
}

// ---------- RFM scan (parallel init) + mask prefixes ----------
__global__ void k_rfm(const int* __restrict__ sc,const int* __restrict__ st,
    const int* __restrict__ mask_t,const int* __restrict__ s_t,
    const int* __restrict__ is_train,int* __restrict__ rstep,int* __restrict__ cstep,
    int* __restrict__ rowp,int* __restrict__ colp)
{
  const int b=blockIdx.x, t=threadIdx.x;
  int* rs=rstep+b*128; int* cs=cstep+b*1024;
  rs[t]=-1;
  for(int i=t;i<1024;i+=128) cs[i]=-1;
  __syncthreads();
  if(t==0){
    bool train = !(is_train && is_train[0]==0);
    if(train){
      int cnt=0;
      for(int s=0;s<128 && cnt<3;s++){
        int pc=sc[b*128+s], pt=st[b*128+s];
        if(rs[pc]!=-1||cs[pt]!=-1) continue;
        int mt=mask_t[b*128+s], ss=s_t[b*128+s];
        rs[pc]=s;
        int l=pt-ss; if(l<0)l=0;
        int r=pt+mt-ss; if(r>1024)r=1024;
        for(int tt=l;tt<r;tt++) cs[tt]=s;
        cnt++;
      }
    }
    int acc=0;
    rowp[b*129]=0;
    for(int i=0;i<128;i++){ acc += (rs[i]>=0); rowp[b*129+i+1]=acc; }
    acc=0;
    colp[b*1025]=0;
    for(int i=0;i<1024;i++){ acc += (cs[i]>=0); colp[b*1025+i+1]=acc; }
  }
}

// ---------- apply mask ----------
__global__ void k_apply(const float* __restrict__ x,const int* __restrict__ rstep,
    const int* __restrict__ cstep,const float* __restrict__ meanT,
    const float* __restrict__ meanF,float* __restrict__ xm)
{
  long i=(long)blockIdx.x*256+threadIdx.x; if(i>=4194304) return;
  int t=(int)(i&1023); int f=(int)((i>>10)&127); int b=(int)(i>>17);
  int rs=rstep[b*128+f], cs=cstep[b*1024+t];
  float v;
  if(rs<0&&cs<0) v=x[i];
  else v=(cs>=rs)? meanT[b*128+f] : meanF[b*1024+t];
  xm[i]=v;
}

// ---------- emb head ----------
__global__ void k_cat(const float* __restrict__ mu,const float* __restrict__ m2,
                      float* __restrict__ cat)
{
  int i=blockIdx.x*256+threadIdx.x; if(i>=131072) return;
  int b=i>>12, d=i&4095;
  float m=mu[i];
  cat[(long)b*8192+d]=m;
  cat[(long)b*8192+4096+d]=sqrtf(fmaxf(m2[i]-m*m,1e-5f));
}
__global__ void __launch_bounds__(256) k_embp(
    const float* __restrict__ cat,const float* __restrict__ We,
    float* __restrict__ part)
{
  __shared__ float cs[32][64];
  const int ks=blockIdx.x, j=threadIdx.x;
  for(int idx=j; idx<32*64; idx+=256){
    int b=idx>>6, ii=idx&63;
    cs[b][ii]=cat[(long)b*8192 + ks*64 + ii];
  }
  __syncthreads();
  float acc[32];
#pragma unroll
  for(int b=0;b<32;b++) acc[b]=0.f;
  for(int ii=0;ii<64;ii++){
    float w=We[((long)ks*64+ii)*256+j];
#pragma unroll
    for(int b=0;b<32;b++) acc[b]+=cs[b][ii]*w;
  }
#pragma unroll
  for(int b=0;b<32;b++) part[((long)ks*32+b)*256+j]=acc[b];
}
__global__ void __launch_bounds__(256) k_embf(
    const float* __restrict__ part,const float* __restrict__ be,
    const float* __restrict__ Wc,const float* __restrict__ bc,
    float* __restrict__ out)
{
  const int b=blockIdx.x, j=threadIdx.x;
  float s=be[j];
  for(int ks=0;ks<128;ks++) s+=part[((long)ks*32+b)*256+j];
  __shared__ float es[256];
  es[j]=s; __syncthreads();
  if(j<2){
    float acc=bc[j];
    for(int q=0;q<256;q++) acc+=es[q]*Wc[q*2+j];
    out[b*2+j]=acc;
  }
}

// ---------- host ----------
static void run_tail(const float* h3,const float* Wa,const float* ba,const float* va,
                     float* attp,float* att,float* alpha,float* mu,float* m2)
{
  k_attp<<<dim3(8,32),256>>>(Wa,h3,attp);
  k_attf<<<2048,256>>>(attp,ba,att);
  k_salpha<<<32,128>>>(att,va,alpha);
  k_mustats<<<16384,256>>>(h3,alpha,mu,m2);
}

extern "C" void kernel_launch(void* const* d_in,const int* in_sizes,int n_in,
                              void* d_out,int out_size)
{
  const float* x =(const float*)d_in[0];
  const float* W1=(const float*)d_in[1]; const float* b1=(const float*)d_in[2];
  const float* W2=(const float*)d_in[3]; const float* b2=(const float*)d_in[4];
  const float* W3=(const float*)d_in[5]; const float* b3=(const float*)d_in[6];
  const float* Wa=(const float*)d_in[7]; const float* ba=(const float*)d_in[8];
  const float* va=(const float*)d_in[9];
  const float* We=(const float*)d_in[10]; const float* be=(const float*)d_in[11];
  const float* Wc=(const float*)d_in[12]; const float* bc=(const float*)d_in[13];
  const int* mask_t=(const int*)d_in[14]; const int* s_t=(const int*)d_in[15];
  const int* is_train = (n_in>16)? (const int*)d_in[16] : nullptr;
  float* out=(float*)d_out;

  float *h1,*h2,*h3,*d1,*d2,*d3,*fam,*xm,*att,*attp,*alpha,*ds,*dap,*mu,*m2,*dMu,*dE2,*gvec;
  float *cat,*ep,*cm,*tm,*meanT,*meanF,*wtf2,*wtb2,*wtf3,*wtb3;
  int *sc,*st,*rstep,*cstep,*rowp,*colp;
  cudaGetSymbolAddress((void**)&h1,g_h1);   cudaGetSymbolAddress((void**)&h2,g_h2);
  cudaGetSymbolAddress((void**)&h3,g_h3);   cudaGetSymbolAddress((void**)&d1,g_d1);
  cudaGetSymbolAddress((void**)&d2,g_d2);   cudaGetSymbolAddress((void**)&d3,g_d3);
  cudaGetSymbolAddress((void**)&fam,g_fam); cudaGetSymbolAddress((void**)&xm,g_xm);
  cudaGetSymbolAddress((void**)&att,g_att); cudaGetSymbolAddress((void**)&attp,g_attp);
  cudaGetSymbolAddress((void**)&alpha,g_alpha); cudaGetSymbolAddress((void**)&ds,g_dsb);
  cudaGetSymbolAddress((void**)&dap,g_dap);
  cudaGetSymbolAddress((void**)&mu,g_mu);   cudaGetSymbolAddress((void**)&m2,g_m2);
  cudaGetSymbolAddress((void**)&dMu,g_dMu); cudaGetSymbolAddress((void**)&dE2,g_dE2);
  cudaGetSymbolAddress((void**)&gvec,g_gvec);
  cudaGetSymbolAddress((void**)&cat,g_cat); cudaGetSymbolAddress((void**)&ep,g_ep);
  cudaGetSymbolAddress((void**)&cm,g_cm);   cudaGetSymbolAddress((void**)&tm,g_tm);
  cudaGetSymbolAddress((void**)&meanT,g_meanT); cudaGetSymbolAddress((void**)&meanF,g_meanF);
  cudaGetSymbolAddress((void**)&sc,g_sc);   cudaGetSymbolAddress((void**)&st,g_st);
  cudaGetSymbolAddress((void**)&rstep,g_rstep); cudaGetSymbolAddress((void**)&cstep,g_cstep);
  cudaGetSymbolAddress((void**)&rowp,g_rowp);   cudaGetSymbolAddress((void**)&colp,g_colp);
  cudaGetSymbolAddress((void**)&wtf2,g_wtf2); cudaGetSymbolAddress((void**)&wtb2,g_wtb2);
  cudaGetSymbolAddress((void**)&wtf3,g_wtf3); cudaGetSymbolAddress((void**)&wtb3,g_wtb3);

  const int SMEM1 = 120*136*4;
  const int SMEM3 = 168*136*4;
  cudaFuncSetAttribute(k_cmma<64,128,64,512,1>,  cudaFuncAttributeMaxDynamicSharedMemorySize, SMEM1);
  cudaFuncSetAttribute(k_cmma<64,128,64,512,3>,  cudaFuncAttributeMaxDynamicSharedMemorySize, SMEM3);
  cudaFuncSetAttribute(k_cmma<128,256,32,256,1>, cudaFuncAttributeMaxDynamicSharedMemorySize, SMEM1);
  cudaFuncSetAttribute(k_cmma<128,256,32,256,3>, cudaFuncAttributeMaxDynamicSharedMemorySize, SMEM3);

  // prep
  k_wt<<<288,256>>>(W2,wtf2,wtb2,64,128);
  k_wt<<<1152,256>>>(W3,wtf3,wtb3,128,256);
  k_gvec<<<1024,256>>>(We,Wc,gvec);
  // pass 1: forward convs 3xTF32 (argsort-critical)
  k_conv1<0><<<dim3(8,64,32),256>>>(x,W1,b1,h1,nullptr,nullptr);
  k_cmma<64,128,64,512,3><<<dim3(2,32,32),256,SMEM3>>>(h1,wtf2,b2,h2);
  k_cmma<128,256,32,256,3><<<dim3(2,16,32),256,SMEM3>>>(h2,wtf3,b3,h3);
  run_tail(h3,Wa,ba,va,attp,att,alpha,mu,m2);
  // backward to input: single-tf32
  k_dcoef<<<512,256>>>(mu,m2,gvec,dMu,dE2);
  k_dalp<<<dim3(8,32),128>>>(h3,dMu,dE2,dap);
  k_dalf<<<32,128>>>(dap,alpha,ds);
  k_dfeat<<<dim3(32,32),256>>>(Wa,att,va,ds,h3,alpha,dMu,dE2,d3);
  k_cbmma<128,256,16,128,128><<<dim3(2,32,32),256>>>(d3,wtb3,h2,d2);
  k_cbmma<64,128,32,256,256><<<dim3(2,64,32),256>>>(d2,wtb2,h1,d1);
  k_bwd1<<<dim3(2,32,32),256>>>(d1,W1,fam);
  // masking
  k_rowstats<<<512,256>>>(fam,x,cm,meanT);
  k_colstats<<<128,256>>>(fam,x,tm,meanF);
  k_sort<128><<<32,64>>>(cm,sc);
  k_sort<1024><<<32,512>>>(tm,st);
  k_rfm<<<32,128>>>(sc,st,mask_t,s_t,is_train,rstep,cstep,rowp,colp);
  k_apply<<<16384,256>>>(x,rstep,cstep,meanT,meanF,xm);
  // pass 2 (single tf32); conv1 with skip, updates h1 in place
  k_conv1<1><<<dim3(8,64,32),256>>>(xm,W1,b1,h1,rowp,colp);
  k_cmma<64,128,64,512,1><<<dim3(2,32,32),256,SMEM1>>>(h1,wtf2,b2,h2);
  k_cmma<128,256,32,256,1><<<dim3(2,16,32),256,SMEM1>>>(h2,wtf3,b3,h3);
  run_tail(h3,Wa,ba,va,attp,att,alpha,mu,m2);
  k_cat<<<512,256>>>(mu,m2,cat);
  k_embp<<<128,256>>>(cat,We,ep);
  k_embf<<<32,256>>>(ep,be,Wc,bc,out);
}